// round 3
// baseline (speedup 1.0000x reference)
#include <cuda_runtime.h>
#include <math.h>

#define BATCH  4
#define SEQ    2048
#define DMODEL 1024
#define NHEAD  16
#define HDIM   64
#define MTOT   (BATCH * SEQ)     // 8192
#define QKVN   (3 * DMODEL)      // 3072

// Scratch (device-global statics: allocation-free per harness rules)
static __device__ float g_xn [MTOT * DMODEL];   // 32 MB
static __device__ float g_qkv[MTOT * QKVN];     // 96 MB
static __device__ float g_ctx[MTOT * DMODEL];   // 32 MB

// ---------------------------------------------------------------------------
// LayerNorm: one block per row (D=1024), 256 threads, float4 per thread
// ---------------------------------------------------------------------------
__global__ __launch_bounds__(256) void ln_kernel(const float* __restrict__ x,
                                                 const float* __restrict__ gamma,
                                                 const float* __restrict__ beta)
{
    const int row = blockIdx.x;
    const int tid = threadIdx.x;
    const float4 v = ((const float4*)(x + (size_t)row * DMODEL))[tid];

    float s  = v.x + v.y + v.z + v.w;
    float s2 = v.x * v.x + v.y * v.y + v.z * v.z + v.w * v.w;
#pragma unroll
    for (int o = 16; o > 0; o >>= 1) {
        s  += __shfl_xor_sync(0xffffffffu, s,  o);
        s2 += __shfl_xor_sync(0xffffffffu, s2, o);
    }
    __shared__ float rs[8], rs2[8], mv[2];
    if ((tid & 31) == 0) { rs[tid >> 5] = s; rs2[tid >> 5] = s2; }
    __syncthreads();
    if (tid == 0) {
        float a = 0.f, b2 = 0.f;
#pragma unroll
        for (int i = 0; i < 8; i++) { a += rs[i]; b2 += rs2[i]; }
        const float mean = a * (1.0f / DMODEL);
        const float var  = b2 * (1.0f / DMODEL) - mean * mean;
        mv[0] = mean;
        mv[1] = rsqrtf(var + 1e-5f);
    }
    __syncthreads();
    const float mean = mv[0], r = mv[1];
    const float4 g  = ((const float4*)gamma)[tid];
    const float4 be = ((const float4*)beta)[tid];
    float4 o;
    o.x = (v.x - mean) * r * g.x + be.x;
    o.y = (v.y - mean) * r * g.y + be.y;
    o.z = (v.z - mean) * r * g.z + be.z;
    o.w = (v.w - mean) * r * g.w + be.w;
    ((float4*)(g_xn + (size_t)row * DMODEL))[tid] = o;
}

// ---------------------------------------------------------------------------
// SGEMM: C[m,n] = sum_k A[m,k] * B[n,k] (+ bias[n])
// A: [M,K] row-major, B: [N,K] row-major. 64x64x32 tiles, 256 thr, 4x4/thread.
// ---------------------------------------------------------------------------
template <bool HAS_BIAS>
__global__ __launch_bounds__(256) void sgemm_tn_kernel(const float* __restrict__ A,
                                                       const float* __restrict__ Bm,
                                                       const float* __restrict__ bias,
                                                       float* __restrict__ C,
                                                       int N, int K)
{
    __shared__ float As[32][68];   // transposed, padded: conflict-free LDS.128
    __shared__ float Bs[32][68];

    const int tid  = threadIdx.x;
    const int tx   = tid & 15;
    const int ty   = tid >> 4;
    const int bm   = blockIdx.y * 64;
    const int bn   = blockIdx.x * 64;
    const int lrow = tid >> 2;            // 0..63
    const int lk   = (tid & 3) * 8;       // 0,8,16,24

    const float* Ap = A  + (size_t)(bm + lrow) * K + lk;
    const float* Bp = Bm + (size_t)(bn + lrow) * K + lk;

    float acc[4][4] = {};

    for (int kt = 0; kt < K; kt += 32) {
        const float4 av0 = *(const float4*)(Ap + kt);
        const float4 av1 = *(const float4*)(Ap + kt + 4);
        const float4 bv0 = *(const float4*)(Bp + kt);
        const float4 bv1 = *(const float4*)(Bp + kt + 4);
        As[lk + 0][lrow] = av0.x; As[lk + 1][lrow] = av0.y;
        As[lk + 2][lrow] = av0.z; As[lk + 3][lrow] = av0.w;
        As[lk + 4][lrow] = av1.x; As[lk + 5][lrow] = av1.y;
        As[lk + 6][lrow] = av1.z; As[lk + 7][lrow] = av1.w;
        Bs[lk + 0][lrow] = bv0.x; Bs[lk + 1][lrow] = bv0.y;
        Bs[lk + 2][lrow] = bv0.z; Bs[lk + 3][lrow] = bv0.w;
        Bs[lk + 4][lrow] = bv1.x; Bs[lk + 5][lrow] = bv1.y;
        Bs[lk + 6][lrow] = bv1.z; Bs[lk + 7][lrow] = bv1.w;
        __syncthreads();
#pragma unroll
        for (int k = 0; k < 32; k++) {
            float af[4], bf[4];
            *(float4*)af = *(const float4*)&As[k][ty * 4];
            *(float4*)bf = *(const float4*)&Bs[k][tx * 4];
#pragma unroll
            for (int i = 0; i < 4; i++)
#pragma unroll
                for (int j = 0; j < 4; j++)
                    acc[i][j] += af[i] * bf[j];
        }
        __syncthreads();
    }

    float bb[4] = {0.f, 0.f, 0.f, 0.f};
    if (HAS_BIAS) {
#pragma unroll
        for (int j = 0; j < 4; j++) bb[j] = bias[bn + tx * 4 + j];
    }
#pragma unroll
    for (int i = 0; i < 4; i++) {
        float4 o;
        o.x = acc[i][0] + bb[0];
        o.y = acc[i][1] + bb[1];
        o.z = acc[i][2] + bb[2];
        o.w = acc[i][3] + bb[3];
        *(float4*)&C[(size_t)(bm + ty * 4 + i) * N + bn + tx * 4] = o;
    }
}

// ---------------------------------------------------------------------------
// Flash-style attention: block = 64 query rows for one (b,h).
// Grid: (SEQ/64, BATCH*NHEAD). 256 threads; 4x4 S/O micro-tile per thread.
// Smem (dynamic, 67584 B): Qs[64][68] (d-major), Ks[64][68] (d-major),
//                          Vs[64][64] (kv-major), Ps[64][64] (q-major)
// ---------------------------------------------------------------------------
#define ATTN_SMEM ((2 * 64 * 68 + 2 * 64 * 64) * 4)

__global__ __launch_bounds__(256) void attn_kernel()
{
    extern __shared__ float smem[];
    float (*Qs)[68] = (float (*)[68])(smem);
    float (*Ks)[68] = (float (*)[68])(smem + 64 * 68);
    float (*Vs)[64] = (float (*)[64])(smem + 2 * 64 * 68);
    float (*Ps)[64] = (float (*)[64])(smem + 2 * 64 * 68 + 64 * 64);

    const int qt  = blockIdx.x;
    const int bh  = blockIdx.y;
    const int b   = bh >> 4;
    const int h   = bh & 15;
    const int tid = threadIdx.x;
    const int tx  = tid & 15;
    const int ty  = tid >> 4;

    const int qoff  = h * HDIM;
    const int koff  = DMODEL + h * HDIM;
    const int voff  = 2 * DMODEL + h * HDIM;
    const int qbase = b * SEQ + qt * 64;

    // Load Q tile (transposed: Qs[d][q])
#pragma unroll
    for (int p = 0; p < 4; p++) {
        const int idx = tid + p * 256;
        const int row = idx >> 4;
        const int c4  = (idx & 15) << 2;
        const float4 v = *(const float4*)(g_qkv + (size_t)(qbase + row) * QKVN + qoff + c4);
        Qs[c4 + 0][row] = v.x; Qs[c4 + 1][row] = v.y;
        Qs[c4 + 2][row] = v.z; Qs[c4 + 3][row] = v.w;
    }

    float m_run[4], l_run[4], O[4][4];
#pragma unroll
    for (int i = 0; i < 4; i++) {
        m_run[i] = -INFINITY;
        l_run[i] = 0.f;
#pragma unroll
        for (int j = 0; j < 4; j++) O[i][j] = 0.f;
    }

    for (int kt = 0; kt < SEQ / 64; kt++) {
        const int kbase = b * SEQ + kt * 64;
        __syncthreads();   // prior-iter smem consumers done (also covers Q-store visibility)
#pragma unroll
        for (int p = 0; p < 4; p++) {
            const int idx = tid + p * 256;
            const int row = idx >> 4;
            const int c4  = (idx & 15) << 2;
            const float* base = g_qkv + (size_t)(kbase + row) * QKVN;
            const float4 kv4 = *(const float4*)(base + koff + c4);
            Ks[c4 + 0][row] = kv4.x; Ks[c4 + 1][row] = kv4.y;
            Ks[c4 + 2][row] = kv4.z; Ks[c4 + 3][row] = kv4.w;
            *(float4*)&Vs[row][c4] = *(const float4*)(base + voff + c4);
        }
        __syncthreads();

        // S = (Q K^T) * scale : per-thread 4x4 over d=64
        float s[4][4] = {};
#pragma unroll 16
        for (int d = 0; d < 64; d++) {
            float af[4], bf[4];
            *(float4*)af = *(const float4*)&Qs[d][ty * 4];
            *(float4*)bf = *(const float4*)&Ks[d][tx * 4];
#pragma unroll
            for (int i = 0; i < 4; i++)
#pragma unroll
                for (int j = 0; j < 4; j++)
                    s[i][j] += af[i] * bf[j];
        }
        const float sc = 0.125f;  // 1/sqrt(64)
#pragma unroll
        for (int i = 0; i < 4; i++)
#pragma unroll
            for (int j = 0; j < 4; j++)
                s[i][j] *= sc;

        // Online softmax per row (row owned by 16 lanes with same ty)
#pragma unroll
        for (int i = 0; i < 4; i++) {
            float m0 = fmaxf(fmaxf(s[i][0], s[i][1]), fmaxf(s[i][2], s[i][3]));
#pragma unroll
            for (int o = 8; o > 0; o >>= 1)
                m0 = fmaxf(m0, __shfl_xor_sync(0xffffffffu, m0, o, 16));
            const float mn = fmaxf(m_run[i], m0);
            const float f  = __expf(m_run[i] - mn);
            m_run[i] = mn;
            float rs = 0.f;
#pragma unroll
            for (int j = 0; j < 4; j++) {
                s[i][j] = __expf(s[i][j] - mn);
                rs += s[i][j];
            }
#pragma unroll
            for (int o = 8; o > 0; o >>= 1)
                rs += __shfl_xor_sync(0xffffffffu, rs, o, 16);
            l_run[i] = l_run[i] * f + rs;
#pragma unroll
            for (int j = 0; j < 4; j++) O[i][j] *= f;
            *(float4*)&Ps[ty * 4 + i][tx * 4] = make_float4(s[i][0], s[i][1], s[i][2], s[i][3]);
        }
        __syncthreads();

        // O += P @ V : per-thread 4x4 over kv=64
#pragma unroll 16
        for (int kv = 0; kv < 64; kv++) {
            float a0 = Ps[ty * 4 + 0][kv];
            float a1 = Ps[ty * 4 + 1][kv];
            float a2 = Ps[ty * 4 + 2][kv];
            float a3 = Ps[ty * 4 + 3][kv];
            float bf[4];
            *(float4*)bf = *(const float4*)&Vs[kv][tx * 4];
#pragma unroll
            for (int j = 0; j < 4; j++) {
                O[0][j] += a0 * bf[j];
                O[1][j] += a1 * bf[j];
                O[2][j] += a2 * bf[j];
                O[3][j] += a3 * bf[j];
            }
        }
    }

    // Normalize and write context: ctx[m, h*64 + d]
#pragma unroll
    for (int i = 0; i < 4; i++) {
        const float inv = 1.0f / l_run[i];
        float4 o;
        o.x = O[i][0] * inv; o.y = O[i][1] * inv;
        o.z = O[i][2] * inv; o.w = O[i][3] * inv;
        *(float4*)&g_ctx[(size_t)(qbase + ty * 4 + i) * DMODEL + h * HDIM + tx * 4] = o;
    }
}

// ---------------------------------------------------------------------------
extern "C" void kernel_launch(void* const* d_in, const int* in_sizes, int n_in,
                              void* d_out, int out_size)
{
    const float* x      = (const float*)d_in[0];
    const float* gamma  = (const float*)d_in[1];
    const float* beta   = (const float*)d_in[2];
    const float* w_qkv  = (const float*)d_in[3];
    const float* w_out  = (const float*)d_in[4];
    const float* b_out  = (const float*)d_in[5];
    float* out = (float*)d_out;

    static float* xn  = nullptr;
    static float* qkv = nullptr;
    static float* ctx = nullptr;
    static bool init = false;
    if (!init) {
        cudaGetSymbolAddress((void**)&xn,  g_xn);
        cudaGetSymbolAddress((void**)&qkv, g_qkv);
        cudaGetSymbolAddress((void**)&ctx, g_ctx);
        cudaFuncSetAttribute(attn_kernel, cudaFuncAttributeMaxDynamicSharedMemorySize, ATTN_SMEM);
        init = true;
    }

    // 1) LayerNorm
    ln_kernel<<<MTOT, 256>>>(x, gamma, beta);

    // 2) QKV projection: [8192,1024] x [3072,1024]^T -> [8192,3072]
    sgemm_tn_kernel<false><<<dim3(QKVN / 64, MTOT / 64), 256>>>(xn, w_qkv, nullptr, qkv, QKVN, DMODEL);

    // 3) Attention
    attn_kernel<<<dim3(SEQ / 64, BATCH * NHEAD), 256, ATTN_SMEM>>>();

    // 4) Output projection + bias: [8192,1024] x [1024,1024]^T -> [8192,1024]
    sgemm_tn_kernel<true><<<dim3(DMODEL / 64, MTOT / 64), 256>>>(ctx, w_out, b_out, out, DMODEL, DMODEL);
}

// round 8
// speedup vs baseline: 1.2336x; 1.2336x over previous
#include <cuda_runtime.h>
#include <math.h>
#include <stdint.h>

#define BATCH  4
#define SEQ    2048
#define DMODEL 1024
#define NHEAD  16
#define HDIM   64
#define MTOT   (BATCH * SEQ)     // 8192
#define QKVN   (3 * DMODEL)      // 3072

// Scratch (device-global statics: allocation-free per harness rules)
static __device__ float g_xn [MTOT * DMODEL];   // 32 MB
static __device__ float g_qkv[MTOT * QKVN];     // 96 MB
static __device__ float g_ctx[MTOT * DMODEL];   // 32 MB

// ---------------------------------------------------------------------------
// LayerNorm: one block per row (D=1024), 256 threads, float4 per thread
// ---------------------------------------------------------------------------
__global__ __launch_bounds__(256) void ln_kernel(const float* __restrict__ x,
                                                 const float* __restrict__ gamma,
                                                 const float* __restrict__ beta)
{
    const int row = blockIdx.x;
    const int tid = threadIdx.x;
    const float4 v = ((const float4*)(x + (size_t)row * DMODEL))[tid];

    float s  = v.x + v.y + v.z + v.w;
    float s2 = v.x * v.x + v.y * v.y + v.z * v.z + v.w * v.w;
#pragma unroll
    for (int o = 16; o > 0; o >>= 1) {
        s  += __shfl_xor_sync(0xffffffffu, s,  o);
        s2 += __shfl_xor_sync(0xffffffffu, s2, o);
    }
    __shared__ float rs[8], rs2[8], mv[2];
    if ((tid & 31) == 0) { rs[tid >> 5] = s; rs2[tid >> 5] = s2; }
    __syncthreads();
    if (tid == 0) {
        float a = 0.f, b2 = 0.f;
#pragma unroll
        for (int i = 0; i < 8; i++) { a += rs[i]; b2 += rs2[i]; }
        const float mean = a * (1.0f / DMODEL);
        const float var  = b2 * (1.0f / DMODEL) - mean * mean;
        mv[0] = mean;
        mv[1] = rsqrtf(var + 1e-5f);
    }
    __syncthreads();
    const float mean = mv[0], r = mv[1];
    const float4 g  = ((const float4*)gamma)[tid];
    const float4 be = ((const float4*)beta)[tid];
    float4 o;
    o.x = (v.x - mean) * r * g.x + be.x;
    o.y = (v.y - mean) * r * g.y + be.y;
    o.z = (v.z - mean) * r * g.z + be.z;
    o.w = (v.w - mean) * r * g.w + be.w;
    ((float4*)(g_xn + (size_t)row * DMODEL))[tid] = o;
}

// ---------------------------------------------------------------------------
// TF32 tensor-core GEMM: C[m,n] = sum_k A[m,k]*B[n,k] (+bias[n])
// A: [M,K] row-major, B: [N,K] row-major (so mma row.col fits directly).
// CTA tile 128(M) x 64(N) x 32(K). 256 threads = 8 warps (4M x 2N),
// warp tile 32x32 = 2(mi) x 4(ni) m16n8k8 fragments, 4 k-steps per k-tile.
// Smem holds fragments in per-lane-major order so the mainloop is pure
// conflict-free LDS.128/LDS.64 feeding HMMA.
// ---------------------------------------------------------------------------
__device__ __forceinline__ unsigned f2tf(float x)
{
    unsigned u;
    asm("cvt.rna.tf32.f32 %0, %1;" : "=r"(u) : "f"(x));
    return u;
}

__device__ __forceinline__ void mma_tf32(float* c, const uint4& a, const uint2& b)
{
    asm volatile("mma.sync.aligned.m16n8k8.row.col.f32.tf32.tf32.f32 "
                 "{%0,%1,%2,%3}, {%4,%5,%6,%7}, {%8,%9}, {%0,%1,%2,%3};\n"
                 : "+f"(c[0]), "+f"(c[1]), "+f"(c[2]), "+f"(c[3])
                 : "r"(a.x), "r"(a.y), "r"(a.z), "r"(a.w),
                   "r"(b.x), "r"(b.y));
}

template <bool HAS_BIAS>
__global__ __launch_bounds__(256) void gemm_tf32_tn(const float* __restrict__ A,
                                                    const float* __restrict__ Bm,
                                                    const float* __restrict__ bias,
                                                    float* __restrict__ C,
                                                    int N, int K)
{
    // Fragment-major smem: Af index = ((mb*4+ks)*32 + lane)*4 + j   (16 KB)
    //                      Bf index = ((nb*4+ks)*32 + lane)*2 + j   ( 8 KB)
    __shared__ unsigned Af[8 * 4 * 32 * 4];
    __shared__ unsigned Bf[8 * 4 * 32 * 2];

    const int tid  = threadIdx.x;
    const int lane = tid & 31;
    const int w    = tid >> 5;
    const int wm   = w >> 1;          // 0..3
    const int wn   = w & 1;           // 0..1
    const int bm   = blockIdx.y * 128;
    const int bn   = blockIdx.x * 64;

    // --- global loader assignments ---
    // A tile 128x32: 2 threads/row, 16 k each (4 float4)
    const int arow = tid >> 1;
    const int akb  = (tid & 1) * 16;
    const float* Ap = A + (size_t)(bm + arow) * K + akb;
    // B tile 64x32: 4 threads/row, 8 k each (2 float4)
    const int brow = tid >> 2;
    const int bkb  = (tid & 3) * 8;
    const float* Bp = Bm + (size_t)(bn + brow) * K + bkb;

    // precomputed scatter offsets (element e adds e*4 / e*2)
    const int amb = arow >> 4, ar = arow & 15, agr = ar & 7, arowhi = ar >> 3;
    int aoff[4];
#pragma unroll
    for (int q = 0; q < 4; q++) {
        const int k0 = akb + q * 4;
        const int ks = k0 >> 3, colhi = (k0 >> 2) & 1;
        aoff[q] = ((amb * 4 + ks) * 32 + agr * 4) * 4 + arowhi + 2 * colhi;
    }
    const int bnb = brow >> 3, bgr = brow & 7;
    int boff[2];
#pragma unroll
    for (int q = 0; q < 2; q++) {
        const int k0 = bkb + q * 4;
        const int ks = k0 >> 3, colhi = (k0 >> 2) & 1;
        boff[q] = ((bnb * 4 + ks) * 32 + bgr * 4) * 2 + colhi;
    }

    float4 areg[4];
    float4 breg[2];
    float acc[2][4][4] = {};

    const int nkt = K >> 5;

    // prologue: fetch k-tile 0
#pragma unroll
    for (int q = 0; q < 4; q++) areg[q] = *(const float4*)(Ap + q * 4);
#pragma unroll
    for (int q = 0; q < 2; q++) breg[q] = *(const float4*)(Bp + q * 4);
#pragma unroll
    for (int q = 0; q < 4; q++) {
        Af[aoff[q]     ] = f2tf(areg[q].x);
        Af[aoff[q] +  4] = f2tf(areg[q].y);
        Af[aoff[q] +  8] = f2tf(areg[q].z);
        Af[aoff[q] + 12] = f2tf(areg[q].w);
    }
#pragma unroll
    for (int q = 0; q < 2; q++) {
        Bf[boff[q]    ] = f2tf(breg[q].x);
        Bf[boff[q] + 2] = f2tf(breg[q].y);
        Bf[boff[q] + 4] = f2tf(breg[q].z);
        Bf[boff[q] + 6] = f2tf(breg[q].w);
    }
    __syncthreads();

    const uint4* Afu = (const uint4*)Af;
    const uint2* Bfu = (const uint2*)Bf;

    for (int kt = 0; kt < nkt; kt++) {
        const bool more = (kt + 1 < nkt);
        if (more) {
            const int koff = (kt + 1) * 32;
#pragma unroll
            for (int q = 0; q < 4; q++) areg[q] = *(const float4*)(Ap + koff + q * 4);
#pragma unroll
            for (int q = 0; q < 2; q++) breg[q] = *(const float4*)(Bp + koff + q * 4);
        }

#pragma unroll
        for (int ks = 0; ks < 4; ks++) {
            uint4 av[2];
            uint2 bv[4];
#pragma unroll
            for (int mi = 0; mi < 2; mi++)
                av[mi] = Afu[((wm * 2 + mi) * 4 + ks) * 32 + lane];
#pragma unroll
            for (int ni = 0; ni < 4; ni++)
                bv[ni] = Bfu[((wn * 4 + ni) * 4 + ks) * 32 + lane];
#pragma unroll
            for (int mi = 0; mi < 2; mi++)
#pragma unroll
                for (int ni = 0; ni < 4; ni++)
                    mma_tf32(acc[mi][ni], av[mi], bv[ni]);
        }

        if (more) {
            __syncthreads();
#pragma unroll
            for (int q = 0; q < 4; q++) {
                Af[aoff[q]     ] = f2tf(areg[q].x);
                Af[aoff[q] +  4] = f2tf(areg[q].y);
                Af[aoff[q] +  8] = f2tf(areg[q].z);
                Af[aoff[q] + 12] = f2tf(areg[q].w);
            }
#pragma unroll
            for (int q = 0; q < 2; q++) {
                Bf[boff[q]    ] = f2tf(breg[q].x);
                Bf[boff[q] + 2] = f2tf(breg[q].y);
                Bf[boff[q] + 4] = f2tf(breg[q].z);
                Bf[boff[q] + 6] = f2tf(breg[q].w);
            }
            __syncthreads();
        }
    }

    // epilogue: c0 (gr, 2gc) c1 (gr, 2gc+1) c2 (gr+8, 2gc) c3 (gr+8, 2gc+1)
    const int gr = lane >> 2, gc = lane & 3;
#pragma unroll
    for (int mi = 0; mi < 2; mi++) {
        const int row0 = bm + wm * 32 + mi * 16 + gr;
#pragma unroll
        for (int ni = 0; ni < 4; ni++) {
            const int col = bn + wn * 32 + ni * 8 + 2 * gc;
            float b0 = 0.f, b1 = 0.f;
            if (HAS_BIAS) { b0 = bias[col]; b1 = bias[col + 1]; }
            float2 v0, v1;
            v0.x = acc[mi][ni][0] + b0; v0.y = acc[mi][ni][1] + b1;
            v1.x = acc[mi][ni][2] + b0; v1.y = acc[mi][ni][3] + b1;
            *(float2*)&C[(size_t)row0 * N + col]       = v0;
            *(float2*)&C[(size_t)(row0 + 8) * N + col] = v1;
        }
    }
}

// ---------------------------------------------------------------------------
// Flash-style attention: block = 64 query rows for one (b,h).
// Grid: (SEQ/64, BATCH*NHEAD). 256 threads; 4x4 S/O micro-tile per thread.
// ---------------------------------------------------------------------------
#define ATTN_SMEM ((2 * 64 * 68 + 2 * 64 * 64) * 4)

__global__ __launch_bounds__(256) void attn_kernel()
{
    extern __shared__ float smem[];
    float (*Qs)[68] = (float (*)[68])(smem);
    float (*Ks)[68] = (float (*)[68])(smem + 64 * 68);
    float (*Vs)[64] = (float (*)[64])(smem + 2 * 64 * 68);
    float (*Ps)[64] = (float (*)[64])(smem + 2 * 64 * 68 + 64 * 64);

    const int qt  = blockIdx.x;
    const int bh  = blockIdx.y;
    const int b   = bh >> 4;
    const int h   = bh & 15;
    const int tid = threadIdx.x;
    const int tx  = tid & 15;
    const int ty  = tid >> 4;

    const int qoff  = h * HDIM;
    const int koff  = DMODEL + h * HDIM;
    const int voff  = 2 * DMODEL + h * HDIM;
    const int qbase = b * SEQ + qt * 64;

#pragma unroll
    for (int p = 0; p < 4; p++) {
        const int idx = tid + p * 256;
        const int row = idx >> 4;
        const int c4  = (idx & 15) << 2;
        const float4 v = *(const float4*)(g_qkv + (size_t)(qbase + row) * QKVN + qoff + c4);
        Qs[c4 + 0][row] = v.x; Qs[c4 + 1][row] = v.y;
        Qs[c4 + 2][row] = v.z; Qs[c4 + 3][row] = v.w;
    }

    float m_run[4], l_run[4], O[4][4];
#pragma unroll
    for (int i = 0; i < 4; i++) {
        m_run[i] = -INFINITY;
        l_run[i] = 0.f;
#pragma unroll
        for (int j = 0; j < 4; j++) O[i][j] = 0.f;
    }

    for (int kt = 0; kt < SEQ / 64; kt++) {
        const int kbase = b * SEQ + kt * 64;
        __syncthreads();
#pragma unroll
        for (int p = 0; p < 4; p++) {
            const int idx = tid + p * 256;
            const int row = idx >> 4;
            const int c4  = (idx & 15) << 2;
            const float* base = g_qkv + (size_t)(kbase + row) * QKVN;
            const float4 kv4 = *(const float4*)(base + koff + c4);
            Ks[c4 + 0][row] = kv4.x; Ks[c4 + 1][row] = kv4.y;
            Ks[c4 + 2][row] = kv4.z; Ks[c4 + 3][row] = kv4.w;
            *(float4*)&Vs[row][c4] = *(const float4*)(base + voff + c4);
        }
        __syncthreads();

        float s[4][4] = {};
#pragma unroll 16
        for (int d = 0; d < 64; d++) {
            float af[4], bf[4];
            *(float4*)af = *(const float4*)&Qs[d][ty * 4];
            *(float4*)bf = *(const float4*)&Ks[d][tx * 4];
#pragma unroll
            for (int i = 0; i < 4; i++)
#pragma unroll
                for (int j = 0; j < 4; j++)
                    s[i][j] += af[i] * bf[j];
        }
        const float sc = 0.125f;
#pragma unroll
        for (int i = 0; i < 4; i++)
#pragma unroll
            for (int j = 0; j < 4; j++)
                s[i][j] *= sc;

#pragma unroll
        for (int i = 0; i < 4; i++) {
            float m0 = fmaxf(fmaxf(s[i][0], s[i][1]), fmaxf(s[i][2], s[i][3]));
#pragma unroll
            for (int o = 8; o > 0; o >>= 1)
                m0 = fmaxf(m0, __shfl_xor_sync(0xffffffffu, m0, o, 16));
            const float mn = fmaxf(m_run[i], m0);
            const float f  = __expf(m_run[i] - mn);
            m_run[i] = mn;
            float rsum = 0.f;
#pragma unroll
            for (int j = 0; j < 4; j++) {
                s[i][j] = __expf(s[i][j] - mn);
                rsum += s[i][j];
            }
#pragma unroll
            for (int o = 8; o > 0; o >>= 1)
                rsum += __shfl_xor_sync(0xffffffffu, rsum, o, 16);
            l_run[i] = l_run[i] * f + rsum;
#pragma unroll
            for (int j = 0; j < 4; j++) O[i][j] *= f;
            *(float4*)&Ps[ty * 4 + i][tx * 4] = make_float4(s[i][0], s[i][1], s[i][2], s[i][3]);
        }
        __syncthreads();

#pragma unroll 16
        for (int kv = 0; kv < 64; kv++) {
            float a0 = Ps[ty * 4 + 0][kv];
            float a1 = Ps[ty * 4 + 1][kv];
            float a2 = Ps[ty * 4 + 2][kv];
            float a3 = Ps[ty * 4 + 3][kv];
            float bf[4];
            *(float4*)bf = *(const float4*)&Vs[kv][tx * 4];
#pragma unroll
            for (int j = 0; j < 4; j++) {
                O[0][j] += a0 * bf[j];
                O[1][j] += a1 * bf[j];
                O[2][j] += a2 * bf[j];
                O[3][j] += a3 * bf[j];
            }
        }
    }

#pragma unroll
    for (int i = 0; i < 4; i++) {
        const float inv = 1.0f / l_run[i];
        float4 o;
        o.x = O[i][0] * inv; o.y = O[i][1] * inv;
        o.z = O[i][2] * inv; o.w = O[i][3] * inv;
        *(float4*)&g_ctx[(size_t)(qbase + ty * 4 + i) * DMODEL + h * HDIM + tx * 4] = o;
    }
}

// ---------------------------------------------------------------------------
extern "C" void kernel_launch(void* const* d_in, const int* in_sizes, int n_in,
                              void* d_out, int out_size)
{
    const float* x      = (const float*)d_in[0];
    const float* gamma  = (const float*)d_in[1];
    const float* beta   = (const float*)d_in[2];
    const float* w_qkv  = (const float*)d_in[3];
    const float* w_out  = (const float*)d_in[4];
    const float* b_out  = (const float*)d_in[5];
    float* out = (float*)d_out;

    static float* xn  = nullptr;
    static float* qkv = nullptr;
    static float* ctx = nullptr;
    static bool init = false;
    if (!init) {
        cudaGetSymbolAddress((void**)&xn,  g_xn);
        cudaGetSymbolAddress((void**)&qkv, g_qkv);
        cudaGetSymbolAddress((void**)&ctx, g_ctx);
        cudaFuncSetAttribute(attn_kernel, cudaFuncAttributeMaxDynamicSharedMemorySize, ATTN_SMEM);
        init = true;
    }

    // 1) LayerNorm
    ln_kernel<<<MTOT, 256>>>(x, gamma, beta);

    // 2) QKV projection: [8192,1024] x [3072,1024]^T -> [8192,3072]  (tf32 MMA)
    gemm_tf32_tn<false><<<dim3(QKVN / 64, MTOT / 128), 256>>>(xn, w_qkv, nullptr, qkv, QKVN, DMODEL);

    // 3) Attention
    attn_kernel<<<dim3(SEQ / 64, BATCH * NHEAD), 256, ATTN_SMEM>>>();

    // 4) Output projection + bias: [8192,1024] x [1024,1024]^T -> [8192,1024]  (tf32 MMA)
    gemm_tf32_tn<true><<<dim3(DMODEL / 64, MTOT / 128), 256>>>(ctx, w_out, b_out, out, DMODEL, DMODEL);
}

// round 10
// speedup vs baseline: 1.5223x; 1.2341x over previous
#include <cuda_runtime.h>
#include <math.h>
#include <stdint.h>

#define BATCH  4
#define SEQ    2048
#define DMODEL 1024
#define NHEAD  16
#define HDIM   64
#define MTOT   (BATCH * SEQ)     // 8192
#define QKVN   (3 * DMODEL)      // 3072

// Scratch (device-global statics: allocation-free per harness rules)
static __device__ float g_xn [MTOT * DMODEL];   // 32 MB
static __device__ float g_qkv[MTOT * QKVN];     // 96 MB
static __device__ float g_ctx[MTOT * DMODEL];   // 32 MB

// ---------------------------------------------------------------------------
// LayerNorm: one block per row (D=1024), 256 threads, float4 per thread
// ---------------------------------------------------------------------------
__global__ __launch_bounds__(256) void ln_kernel(const float* __restrict__ x,
                                                 const float* __restrict__ gamma,
                                                 const float* __restrict__ beta)
{
    const int row = blockIdx.x;
    const int tid = threadIdx.x;
    const float4 v = ((const float4*)(x + (size_t)row * DMODEL))[tid];

    float s  = v.x + v.y + v.z + v.w;
    float s2 = v.x * v.x + v.y * v.y + v.z * v.z + v.w * v.w;
#pragma unroll
    for (int o = 16; o > 0; o >>= 1) {
        s  += __shfl_xor_sync(0xffffffffu, s,  o);
        s2 += __shfl_xor_sync(0xffffffffu, s2, o);
    }
    __shared__ float rs[8], rs2[8], mv[2];
    if ((tid & 31) == 0) { rs[tid >> 5] = s; rs2[tid >> 5] = s2; }
    __syncthreads();
    if (tid == 0) {
        float a = 0.f, b2 = 0.f;
#pragma unroll
        for (int i = 0; i < 8; i++) { a += rs[i]; b2 += rs2[i]; }
        const float mean = a * (1.0f / DMODEL);
        const float var  = b2 * (1.0f / DMODEL) - mean * mean;
        mv[0] = mean;
        mv[1] = rsqrtf(var + 1e-5f);
    }
    __syncthreads();
    const float mean = mv[0], r = mv[1];
    const float4 g  = ((const float4*)gamma)[tid];
    const float4 be = ((const float4*)beta)[tid];
    float4 o;
    o.x = (v.x - mean) * r * g.x + be.x;
    o.y = (v.y - mean) * r * g.y + be.y;
    o.z = (v.z - mean) * r * g.z + be.z;
    o.w = (v.w - mean) * r * g.w + be.w;
    ((float4*)(g_xn + (size_t)row * DMODEL))[tid] = o;
}

// ---------------------------------------------------------------------------
// TF32 helpers
// ---------------------------------------------------------------------------
__device__ __forceinline__ unsigned f2tf(float x)
{
    unsigned u;
    asm("cvt.rna.tf32.f32 %0, %1;" : "=r"(u) : "f"(x));
    return u;
}

__device__ __forceinline__ void mma_tf32(float* c, const uint4& a, const uint2& b)
{
    asm volatile("mma.sync.aligned.m16n8k8.row.col.f32.tf32.tf32.f32 "
                 "{%0,%1,%2,%3}, {%4,%5,%6,%7}, {%8,%9}, {%0,%1,%2,%3};\n"
                 : "+f"(c[0]), "+f"(c[1]), "+f"(c[2]), "+f"(c[3])
                 : "r"(a.x), "r"(a.y), "r"(a.z), "r"(a.w),
                   "r"(b.x), "r"(b.y));
}

// ---------------------------------------------------------------------------
// TF32 tensor-core GEMM: C[m,n] = sum_k A[m,k]*B[n,k] (+bias[n])
// (unchanged from round 8 — validated)
// ---------------------------------------------------------------------------
template <bool HAS_BIAS>
__global__ __launch_bounds__(256) void gemm_tf32_tn(const float* __restrict__ A,
                                                    const float* __restrict__ Bm,
                                                    const float* __restrict__ bias,
                                                    float* __restrict__ C,
                                                    int N, int K)
{
    __shared__ unsigned Af[8 * 4 * 32 * 4];
    __shared__ unsigned Bf[8 * 4 * 32 * 2];

    const int tid  = threadIdx.x;
    const int lane = tid & 31;
    const int w    = tid >> 5;
    const int wm   = w >> 1;
    const int wn   = w & 1;
    const int bm   = blockIdx.y * 128;
    const int bn   = blockIdx.x * 64;

    const int arow = tid >> 1;
    const int akb  = (tid & 1) * 16;
    const float* Ap = A + (size_t)(bm + arow) * K + akb;
    const int brow = tid >> 2;
    const int bkb  = (tid & 3) * 8;
    const float* Bp = Bm + (size_t)(bn + brow) * K + bkb;

    const int amb = arow >> 4, ar = arow & 15, agr = ar & 7, arowhi = ar >> 3;
    int aoff[4];
#pragma unroll
    for (int q = 0; q < 4; q++) {
        const int k0 = akb + q * 4;
        const int ks = k0 >> 3, colhi = (k0 >> 2) & 1;
        aoff[q] = ((amb * 4 + ks) * 32 + agr * 4) * 4 + arowhi + 2 * colhi;
    }
    const int bnb = brow >> 3, bgr = brow & 7;
    int boff[2];
#pragma unroll
    for (int q = 0; q < 2; q++) {
        const int k0 = bkb + q * 4;
        const int ks = k0 >> 3, colhi = (k0 >> 2) & 1;
        boff[q] = ((bnb * 4 + ks) * 32 + bgr * 4) * 2 + colhi;
    }

    float4 areg[4];
    float4 breg[2];
    float acc[2][4][4] = {};

    const int nkt = K >> 5;

#pragma unroll
    for (int q = 0; q < 4; q++) areg[q] = *(const float4*)(Ap + q * 4);
#pragma unroll
    for (int q = 0; q < 2; q++) breg[q] = *(const float4*)(Bp + q * 4);
#pragma unroll
    for (int q = 0; q < 4; q++) {
        Af[aoff[q]     ] = f2tf(areg[q].x);
        Af[aoff[q] +  4] = f2tf(areg[q].y);
        Af[aoff[q] +  8] = f2tf(areg[q].z);
        Af[aoff[q] + 12] = f2tf(areg[q].w);
    }
#pragma unroll
    for (int q = 0; q < 2; q++) {
        Bf[boff[q]    ] = f2tf(breg[q].x);
        Bf[boff[q] + 2] = f2tf(breg[q].y);
        Bf[boff[q] + 4] = f2tf(breg[q].z);
        Bf[boff[q] + 6] = f2tf(breg[q].w);
    }
    __syncthreads();

    const uint4* Afu = (const uint4*)Af;
    const uint2* Bfu = (const uint2*)Bf;

    for (int kt = 0; kt < nkt; kt++) {
        const bool more = (kt + 1 < nkt);
        if (more) {
            const int koff = (kt + 1) * 32;
#pragma unroll
            for (int q = 0; q < 4; q++) areg[q] = *(const float4*)(Ap + koff + q * 4);
#pragma unroll
            for (int q = 0; q < 2; q++) breg[q] = *(const float4*)(Bp + koff + q * 4);
        }

#pragma unroll
        for (int ks = 0; ks < 4; ks++) {
            uint4 av[2];
            uint2 bv[4];
#pragma unroll
            for (int mi = 0; mi < 2; mi++)
                av[mi] = Afu[((wm * 2 + mi) * 4 + ks) * 32 + lane];
#pragma unroll
            for (int ni = 0; ni < 4; ni++)
                bv[ni] = Bfu[((wn * 4 + ni) * 4 + ks) * 32 + lane];
#pragma unroll
            for (int mi = 0; mi < 2; mi++)
#pragma unroll
                for (int ni = 0; ni < 4; ni++)
                    mma_tf32(acc[mi][ni], av[mi], bv[ni]);
        }

        if (more) {
            __syncthreads();
#pragma unroll
            for (int q = 0; q < 4; q++) {
                Af[aoff[q]     ] = f2tf(areg[q].x);
                Af[aoff[q] +  4] = f2tf(areg[q].y);
                Af[aoff[q] +  8] = f2tf(areg[q].z);
                Af[aoff[q] + 12] = f2tf(areg[q].w);
            }
#pragma unroll
            for (int q = 0; q < 2; q++) {
                Bf[boff[q]    ] = f2tf(breg[q].x);
                Bf[boff[q] + 2] = f2tf(breg[q].y);
                Bf[boff[q] + 4] = f2tf(breg[q].z);
                Bf[boff[q] + 6] = f2tf(breg[q].w);
            }
            __syncthreads();
        }
    }

    const int gr = lane >> 2, gc = lane & 3;
#pragma unroll
    for (int mi = 0; mi < 2; mi++) {
        const int row0 = bm + wm * 32 + mi * 16 + gr;
#pragma unroll
        for (int ni = 0; ni < 4; ni++) {
            const int col = bn + wn * 32 + ni * 8 + 2 * gc;
            float b0 = 0.f, b1 = 0.f;
            if (HAS_BIAS) { b0 = bias[col]; b1 = bias[col + 1]; }
            float2 v0, v1;
            v0.x = acc[mi][ni][0] + b0; v0.y = acc[mi][ni][1] + b1;
            v1.x = acc[mi][ni][2] + b0; v1.y = acc[mi][ni][3] + b1;
            *(float2*)&C[(size_t)row0 * N + col]       = v0;
            *(float2*)&C[(size_t)(row0 + 8) * N + col] = v1;
        }
    }
}

// ---------------------------------------------------------------------------
// TF32 MMA flash attention. CTA = 64 q-rows of one (b,h); 128 threads (4 warps),
// warp w owns q-rows [w*16, w*16+16). kv loop over 64-wide chunks.
// Smem (64 KB dynamic, all fragment-major unsigned):
//   Qf[4mb][8ks][32][4]  A-frags of Q (scale folded)   16KB
//   Kf[8nb][8ks][32][2]  B-frags of K (S = Q K^T)      16KB
//   Vf[8nb][8ks][32][2]  B-frags of V (O += P V)       16KB
//   Pf[4mb][8ks][32][4]  A-frags of P (warp-private)   16KB
// ---------------------------------------------------------------------------
#define ATTN_SMEM (16384 * 4)

__global__ __launch_bounds__(128, 3) void attn_kernel()
{
    extern __shared__ unsigned fr[];
    unsigned* Qf = fr;
    unsigned* Kf = fr + 4096;
    unsigned* Vf = fr + 8192;
    unsigned* Pf = fr + 12288;

    const int qt   = blockIdx.x;
    const int bh   = blockIdx.y;
    const int b    = bh >> 4;
    const int h    = bh & 15;
    const int tid  = threadIdx.x;
    const int lane = tid & 31;
    const int wid  = tid >> 5;
    const int gr   = lane >> 2;
    const int gc   = lane & 3;

    const int qoff  = h * HDIM;
    const int koff  = DMODEL + h * HDIM;
    const int voff  = 2 * DMODEL + h * HDIM;
    const int qbase = b * SEQ + qt * 64;
    const int kvbas = b * SEQ;

    // ---- loader geometry: 128 threads, tile 64 rows x 64 cols, 8 float4 each
    const int lrow = tid >> 1;            // 0..63
    const int ld0  = (tid & 1) * 32;      // 0 or 32

    // ---- load Q once (scale 1/8 folded), scatter to A-frags
    {
        const int mb = lrow >> 4, rr = lrow & 15, qgr = rr & 7, rowhi = rr >> 3;
        const float* src = g_qkv + (size_t)(qbase + lrow) * QKVN + qoff + ld0;
#pragma unroll
        for (int q = 0; q < 8; q++) {
            const int d = ld0 + q * 4;
            const int ks = d >> 3, colhi = (d >> 2) & 1;
            const float4 v = *(const float4*)(src + q * 4);
            const int i0 = ((mb * 8 + ks) * 32 + qgr * 4) * 4 + rowhi + 2 * colhi;
            Qf[i0     ] = f2tf(v.x * 0.125f);
            Qf[i0 +  4] = f2tf(v.y * 0.125f);
            Qf[i0 +  8] = f2tf(v.z * 0.125f);
            Qf[i0 + 12] = f2tf(v.w * 0.125f);
        }
    }

    float m_run[2] = {-INFINITY, -INFINITY};
    float l_run[2] = {0.f, 0.f};
    float oacc[8][4] = {};

    const uint4* QfU = (const uint4*)Qf;
    const uint2* KfU = (const uint2*)Kf;
    const uint2* VfU = (const uint2*)Vf;
    const uint4* PfU = (const uint4*)Pf;

    for (int kt = 0; kt < SEQ / 64; kt++) {
        __syncthreads();   // previous chunk's MMAs done before overwriting K/V

        // ---- load K chunk -> B-frags (n=kv, k=d); V chunk -> B-frags (k=kv, n=d)
        {
            const int kv = lrow;
            const int knb = kv >> 3, kgr = kv & 7;           // K: n index bits
            const int vks = kv >> 3, vgc = kv & 3, vj = (kv >> 2) & 1;  // V: k index bits
            const float* srck = g_qkv + (size_t)(kvbas + kt * 64 + kv) * QKVN + koff + ld0;
            const float* srcv = g_qkv + (size_t)(kvbas + kt * 64 + kv) * QKVN + voff + ld0;
#pragma unroll
            for (int q = 0; q < 8; q++) {
                const int d = ld0 + q * 4;
                const int ks = d >> 3, colhi = (d >> 2) & 1;
                const float4 vk = *(const float4*)(srck + q * 4);
                const int ik = ((knb * 8 + ks) * 32 + kgr * 4) * 2 + colhi;
                Kf[ik    ] = f2tf(vk.x);
                Kf[ik + 2] = f2tf(vk.y);
                Kf[ik + 4] = f2tf(vk.z);
                Kf[ik + 6] = f2tf(vk.w);

                const int vnb = d >> 3, vgb = d & 7;         // V: n=d bits
                const float4 vv = *(const float4*)(srcv + q * 4);
                const int iv = ((vnb * 8 + vks) * 32 + vgb * 4 + vgc) * 2 + vj;
                Vf[iv     ] = f2tf(vv.x);
                Vf[iv +  8] = f2tf(vv.y);
                Vf[iv + 16] = f2tf(vv.z);
                Vf[iv + 24] = f2tf(vv.w);
            }
        }
        __syncthreads();

        // ---- S = Q K^T (warp: 16 x 64 over d=64)
        float sacc[8][4] = {};
#pragma unroll
        for (int ks = 0; ks < 8; ks++) {
            const uint4 av = QfU[(wid * 8 + ks) * 32 + lane];
#pragma unroll
            for (int nf = 0; nf < 8; nf++) {
                const uint2 bv = KfU[(nf * 8 + ks) * 32 + lane];
                mma_tf32(sacc[nf], av, bv);
            }
        }

        // ---- online softmax on C-frags (rows gr, gr+8)
        float mlo = -INFINITY, mhi = -INFINITY;
#pragma unroll
        for (int nf = 0; nf < 8; nf++) {
            mlo = fmaxf(mlo, fmaxf(sacc[nf][0], sacc[nf][1]));
            mhi = fmaxf(mhi, fmaxf(sacc[nf][2], sacc[nf][3]));
        }
#pragma unroll
        for (int o = 1; o <= 2; o <<= 1) {
            mlo = fmaxf(mlo, __shfl_xor_sync(0xffffffffu, mlo, o));
            mhi = fmaxf(mhi, __shfl_xor_sync(0xffffffffu, mhi, o));
        }
        const float mnlo = fmaxf(m_run[0], mlo);
        const float mnhi = fmaxf(m_run[1], mhi);
        const float flo  = __expf(m_run[0] - mnlo);
        const float fhi  = __expf(m_run[1] - mnhi);
        m_run[0] = mnlo; m_run[1] = mnhi;

        float rslo = 0.f, rshi = 0.f;
        const int cc = 2 * gc;
        const int pbase = ((wid * 8) * 32 + gr * 4 + (cc & 3)) * 4 + 2 * ((cc >> 2) & 1);
#pragma unroll
        for (int nf = 0; nf < 8; nf++) {
            float p0 = __expf(sacc[nf][0] - mnlo);
            float p1 = __expf(sacc[nf][1] - mnlo);
            float p2 = __expf(sacc[nf][2] - mnhi);
            float p3 = __expf(sacc[nf][3] - mnhi);
            rslo += p0 + p1;
            rshi += p2 + p3;
            const int ip = pbase + nf * 128;
            Pf[ip    ] = f2tf(p0);
            Pf[ip + 4] = f2tf(p1);
            Pf[ip + 1] = f2tf(p2);
            Pf[ip + 5] = f2tf(p3);
        }
#pragma unroll
        for (int o = 1; o <= 2; o <<= 1) {
            rslo += __shfl_xor_sync(0xffffffffu, rslo, o);
            rshi += __shfl_xor_sync(0xffffffffu, rshi, o);
        }
        l_run[0] = l_run[0] * flo + rslo;
        l_run[1] = l_run[1] * fhi + rshi;
#pragma unroll
        for (int nd = 0; nd < 8; nd++) {
            oacc[nd][0] *= flo; oacc[nd][1] *= flo;
            oacc[nd][2] *= fhi; oacc[nd][3] *= fhi;
        }
        __syncwarp();   // Pf (warp-private) visible to own warp's MMA loads

        // ---- O += P V (warp: 16 x 64 over kv=64)
#pragma unroll
        for (int ksv = 0; ksv < 8; ksv++) {
            const uint4 av = PfU[(wid * 8 + ksv) * 32 + lane];
#pragma unroll
            for (int nd = 0; nd < 8; nd++) {
                const uint2 bv = VfU[(nd * 8 + ksv) * 32 + lane];
                mma_tf32(oacc[nd], av, bv);
            }
        }
    }

    // ---- normalize + write ctx
    const float invlo = 1.0f / l_run[0];
    const float invhi = 1.0f / l_run[1];
    const int row_lo = qbase + wid * 16 + gr;
#pragma unroll
    for (int nd = 0; nd < 8; nd++) {
        const int col = h * HDIM + nd * 8 + 2 * gc;
        float2 v0, v1;
        v0.x = oacc[nd][0] * invlo; v0.y = oacc[nd][1] * invlo;
        v1.x = oacc[nd][2] * invhi; v1.y = oacc[nd][3] * invhi;
        *(float2*)&g_ctx[(size_t)row_lo * DMODEL + col]       = v0;
        *(float2*)&g_ctx[(size_t)(row_lo + 8) * DMODEL + col] = v1;
    }
}

// ---------------------------------------------------------------------------
extern "C" void kernel_launch(void* const* d_in, const int* in_sizes, int n_in,
                              void* d_out, int out_size)
{
    const float* x      = (const float*)d_in[0];
    const float* gamma  = (const float*)d_in[1];
    const float* beta   = (const float*)d_in[2];
    const float* w_qkv  = (const float*)d_in[3];
    const float* w_out  = (const float*)d_in[4];
    const float* b_out  = (const float*)d_in[5];
    float* out = (float*)d_out;

    static float* xn  = nullptr;
    static float* qkv = nullptr;
    static float* ctx = nullptr;
    static bool init = false;
    if (!init) {
        cudaGetSymbolAddress((void**)&xn,  g_xn);
        cudaGetSymbolAddress((void**)&qkv, g_qkv);
        cudaGetSymbolAddress((void**)&ctx, g_ctx);
        cudaFuncSetAttribute(attn_kernel, cudaFuncAttributeMaxDynamicSharedMemorySize, ATTN_SMEM);
        init = true;
    }

    // 1) LayerNorm
    ln_kernel<<<MTOT, 256>>>(x, gamma, beta);

    // 2) QKV projection: [8192,1024] x [3072,1024]^T -> [8192,3072]  (tf32 MMA)
    gemm_tf32_tn<false><<<dim3(QKVN / 64, MTOT / 128), 256>>>(xn, w_qkv, nullptr, qkv, QKVN, DMODEL);

    // 3) Attention (tf32 MMA flash)
    attn_kernel<<<dim3(SEQ / 64, BATCH * NHEAD), 128, ATTN_SMEM>>>();

    // 4) Output projection + bias: [8192,1024] x [1024,1024]^T -> [8192,1024]  (tf32 MMA)
    gemm_tf32_tn<true><<<dim3(DMODEL / 64, MTOT / 128), 256>>>(ctx, w_out, b_out, out, DMODEL, DMODEL);
}

// round 12
// speedup vs baseline: 1.8605x; 1.2222x over previous
#include <cuda_runtime.h>
#include <math.h>
#include <stdint.h>

#define BATCH  4
#define SEQ    2048
#define DMODEL 1024
#define NHEAD  16
#define HDIM   64
#define MTOT   (BATCH * SEQ)     // 8192
#define QKVN   (3 * DMODEL)      // 3072

// Scratch (device-global statics: allocation-free per harness rules)
static __device__ float g_xn [MTOT * DMODEL];   // 32 MB
static __device__ float g_qkv[MTOT * QKVN];     // 96 MB
static __device__ float g_ctx[MTOT * DMODEL];   // 32 MB

// ---------------------------------------------------------------------------
// TF32 helpers
// ---------------------------------------------------------------------------
__device__ __forceinline__ unsigned f2tf(float x)
{
    unsigned u;
    asm("cvt.rna.tf32.f32 %0, %1;" : "=r"(u) : "f"(x));
    return u;
}

__device__ __forceinline__ void mma_tf32(float* c, const uint4& a, const uint2& b)
{
    asm volatile("mma.sync.aligned.m16n8k8.row.col.f32.tf32.tf32.f32 "
                 "{%0,%1,%2,%3}, {%4,%5,%6,%7}, {%8,%9}, {%0,%1,%2,%3};\n"
                 : "+f"(c[0]), "+f"(c[1]), "+f"(c[2]), "+f"(c[3])
                 : "r"(a.x), "r"(a.y), "r"(a.z), "r"(a.w),
                   "r"(b.x), "r"(b.y));
}

// ---------------------------------------------------------------------------
// LayerNorm: one block per row (D=1024), 256 threads, float4 per thread
// ---------------------------------------------------------------------------
__global__ __launch_bounds__(256) void ln_kernel(const float* __restrict__ x,
                                                 const float* __restrict__ gamma,
                                                 const float* __restrict__ beta)
{
    const int row = blockIdx.x;
    const int tid = threadIdx.x;
    const float4 v = ((const float4*)(x + (size_t)row * DMODEL))[tid];

    float s  = v.x + v.y + v.z + v.w;
    float s2 = v.x * v.x + v.y * v.y + v.z * v.z + v.w * v.w;
#pragma unroll
    for (int o = 16; o > 0; o >>= 1) {
        s  += __shfl_xor_sync(0xffffffffu, s,  o);
        s2 += __shfl_xor_sync(0xffffffffu, s2, o);
    }
    __shared__ float rs[8], rs2[8], mv[2];
    if ((tid & 31) == 0) { rs[tid >> 5] = s; rs2[tid >> 5] = s2; }
    __syncthreads();
    if (tid == 0) {
        float a = 0.f, b2 = 0.f;
#pragma unroll
        for (int i = 0; i < 8; i++) { a += rs[i]; b2 += rs2[i]; }
        const float mean = a * (1.0f / DMODEL);
        const float var  = b2 * (1.0f / DMODEL) - mean * mean;
        mv[0] = mean;
        mv[1] = rsqrtf(var + 1e-5f);
    }
    __syncthreads();
    const float mean = mv[0], r = mv[1];
    const float4 g  = ((const float4*)gamma)[tid];
    const float4 be = ((const float4*)beta)[tid];
    float4 o;
    o.x = (v.x - mean) * r * g.x + be.x;
    o.y = (v.y - mean) * r * g.y + be.y;
    o.z = (v.z - mean) * r * g.z + be.z;
    o.w = (v.w - mean) * r * g.w + be.w;
    ((float4*)(g_xn + (size_t)row * DMODEL))[tid] = o;
}

// ===========================================================================
// TF32 MMA GEMM v3: C[m,n] = sum_k A[m,k]*B[n,k] (+bias[n])
// CTA 128x128x32, 128 threads = 4 warps (wm x wn = 2x2), warp tile 64x64.
// Fragment smem with j-OUTER padded planes (conflict-free STS.128 loaders,
// conflict-free LDS.32 consumers):
//   A: Af[j=0..3][plane 1028 w]  frag fa = mb*4+ks (mb 0..7), word fa*32+lane
//   B: Bf[j=0..1][plane 2052 w]  frag fb = nb*4+ks (nb 0..15), word fb*32+lane
// Double-buffered: stage stride 8216 words; smem total 65728 B.
// ===========================================================================
#define GV_APLANE  1028
#define GV_BPLANE  2052
#define GV_AREG    (4 * GV_APLANE)                 // 4112 words (B region start)
#define GV_STAGE   (GV_AREG + 2 * GV_BPLANE)       // 8216 words
#define GV_SMEM    (2 * GV_STAGE * 4)              // 65728 bytes

template <bool HAS_BIAS>
__global__ __launch_bounds__(128, 2) void gemm_v3_tn(const float* __restrict__ A,
                                                     const float* __restrict__ Bm,
                                                     const float* __restrict__ bias,
                                                     float* __restrict__ C,
                                                     int N, int K)
{
    extern __shared__ unsigned sw[];

    const int tid  = threadIdx.x;
    const int lane = tid & 31;
    const int wid  = tid >> 5;
    const int wm   = wid >> 1;          // 0..1
    const int wn   = wid & 1;           // 0..1
    const int bm   = blockIdx.y * 128;
    const int bn   = blockIdx.x * 128;

    // ---- loader: thread owns row `tid` of both A (m) and B (n) tiles
    const float* Ap = A  + (size_t)(bm + tid) * K;
    const float* Bp = Bm + (size_t)(bn + tid) * K;

    // precomputed word offsets per float4 q (k0 = 4q)
    int aoffw[8], boffw[8];
    {
        const int mbA = tid >> 4, arr = tid & 15, agr = arr & 7, rowhi = arr >> 3;
        const int nbB = tid >> 3, bgr = tid & 7;
#pragma unroll
        for (int q = 0; q < 8; q++) {
            const int ks = q >> 1, chi = q & 1;
            aoffw[q] = (rowhi + 2 * chi) * GV_APLANE + (mbA * 4 + ks) * 32 + agr * 4;
            boffw[q] = GV_AREG + chi * GV_BPLANE + (nbB * 4 + ks) * 32 + bgr * 4;
        }
    }

    float acc[4][8][4] = {};
    const int nc = K >> 5;              // 32 k-chunks

    // ---- prologue: chunk 0 -> stage 0
    {
        float4 av[8], bv[8];
#pragma unroll
        for (int q = 0; q < 8; q++) { av[q] = *(const float4*)(Ap + q * 4);
                                      bv[q] = *(const float4*)(Bp + q * 4); }
#pragma unroll
        for (int q = 0; q < 8; q++) {
            *(uint4*)(sw + aoffw[q]) = make_uint4(f2tf(av[q].x), f2tf(av[q].y),
                                                  f2tf(av[q].z), f2tf(av[q].w));
            *(uint4*)(sw + boffw[q]) = make_uint4(f2tf(bv[q].x), f2tf(bv[q].y),
                                                  f2tf(bv[q].z), f2tf(bv[q].w));
        }
    }
    __syncthreads();

    for (int c = 0; c < nc; c++) {
        const bool more = (c + 1 < nc);
        float4 av[8], bv[8];
        if (more) {
            const int kc = (c + 1) * 32;
#pragma unroll
            for (int q = 0; q < 8; q++) { av[q] = *(const float4*)(Ap + kc + q * 4);
                                          bv[q] = *(const float4*)(Bp + kc + q * 4); }
        }

        // ---- MMA on current stage (LDG above drains underneath)
        const unsigned* bufc = sw + (c & 1) * GV_STAGE;
#pragma unroll
        for (int ks = 0; ks < 4; ks++) {
            uint4 a[4];
            uint2 b[8];
#pragma unroll
            for (int mi = 0; mi < 4; mi++) {
                const int base = ((wm * 4 + mi) * 4 + ks) * 32 + lane;
                a[mi] = make_uint4(bufc[base],
                                   bufc[GV_APLANE     + base],
                                   bufc[2 * GV_APLANE + base],
                                   bufc[3 * GV_APLANE + base]);
            }
#pragma unroll
            for (int ni = 0; ni < 8; ni++) {
                const int base = GV_AREG + ((wn * 8 + ni) * 4 + ks) * 32 + lane;
                b[ni] = make_uint2(bufc[base], bufc[GV_BPLANE + base]);
            }
#pragma unroll
            for (int mi = 0; mi < 4; mi++)
#pragma unroll
                for (int ni = 0; ni < 8; ni++)
                    mma_tf32(acc[mi][ni], a[mi], b[ni]);
        }

        // ---- store prefetched chunk into other stage
        if (more) {
            unsigned* bufn = sw + ((c + 1) & 1) * GV_STAGE;
#pragma unroll
            for (int q = 0; q < 8; q++) {
                *(uint4*)(bufn + aoffw[q]) = make_uint4(f2tf(av[q].x), f2tf(av[q].y),
                                                        f2tf(av[q].z), f2tf(av[q].w));
                *(uint4*)(bufn + boffw[q]) = make_uint4(f2tf(bv[q].x), f2tf(bv[q].y),
                                                        f2tf(bv[q].z), f2tf(bv[q].w));
            }
        }
        __syncthreads();
    }

    // ---- epilogue
    const int gr = lane >> 2, gc = lane & 3;
#pragma unroll
    for (int mi = 0; mi < 4; mi++) {
        const int row0 = bm + wm * 64 + mi * 16 + gr;
#pragma unroll
        for (int ni = 0; ni < 8; ni++) {
            const int col = bn + wn * 64 + ni * 8 + 2 * gc;
            float b0 = 0.f, b1 = 0.f;
            if (HAS_BIAS) { b0 = bias[col]; b1 = bias[col + 1]; }
            float2 v0, v1;
            v0.x = acc[mi][ni][0] + b0; v0.y = acc[mi][ni][1] + b1;
            v1.x = acc[mi][ni][2] + b0; v1.y = acc[mi][ni][3] + b1;
            *(float2*)&C[(size_t)row0 * N + col]       = v0;
            *(float2*)&C[(size_t)(row0 + 8) * N + col] = v1;
        }
    }
}

// ---------------------------------------------------------------------------
// TF32 MMA flash attention (unchanged from round 10 — validated, 2600us cfg)
// ---------------------------------------------------------------------------
#define ATTN_SMEM (16384 * 4)

__global__ __launch_bounds__(128, 3) void attn_kernel()
{
    extern __shared__ unsigned fr[];
    unsigned* Qf = fr;
    unsigned* Kf = fr + 4096;
    unsigned* Vf = fr + 8192;
    unsigned* Pf = fr + 12288;

    const int qt   = blockIdx.x;
    const int bh   = blockIdx.y;
    const int b    = bh >> 4;
    const int h    = bh & 15;
    const int tid  = threadIdx.x;
    const int lane = tid & 31;
    const int wid  = tid >> 5;
    const int gr   = lane >> 2;
    const int gc   = lane & 3;

    const int qoff  = h * HDIM;
    const int koff  = DMODEL + h * HDIM;
    const int voff  = 2 * DMODEL + h * HDIM;
    const int qbase = b * SEQ + qt * 64;
    const int kvbas = b * SEQ;

    const int lrow = tid >> 1;
    const int ld0  = (tid & 1) * 32;

    {
        const int mb = lrow >> 4, rr = lrow & 15, qgr = rr & 7, rowhi = rr >> 3;
        const float* src = g_qkv + (size_t)(qbase + lrow) * QKVN + qoff + ld0;
#pragma unroll
        for (int q = 0; q < 8; q++) {
            const int d = ld0 + q * 4;
            const int ks = d >> 3, colhi = (d >> 2) & 1;
            const float4 v = *(const float4*)(src + q * 4);
            const int i0 = ((mb * 8 + ks) * 32 + qgr * 4) * 4 + rowhi + 2 * colhi;
            Qf[i0     ] = f2tf(v.x * 0.125f);
            Qf[i0 +  4] = f2tf(v.y * 0.125f);
            Qf[i0 +  8] = f2tf(v.z * 0.125f);
            Qf[i0 + 12] = f2tf(v.w * 0.125f);
        }
    }

    float m_run[2] = {-INFINITY, -INFINITY};
    float l_run[2] = {0.f, 0.f};
    float oacc[8][4] = {};

    const uint4* QfU = (const uint4*)Qf;
    const uint2* KfU = (const uint2*)Kf;
    const uint2* VfU = (const uint2*)Vf;
    const uint4* PfU = (const uint4*)Pf;

    for (int kt = 0; kt < SEQ / 64; kt++) {
        __syncthreads();

        {
            const int kv = lrow;
            const int knb = kv >> 3, kgr = kv & 7;
            const int vks = kv >> 3, vgc = kv & 3, vj = (kv >> 2) & 1;
            const float* srck = g_qkv + (size_t)(kvbas + kt * 64 + kv) * QKVN + koff + ld0;
            const float* srcv = g_qkv + (size_t)(kvbas + kt * 64 + kv) * QKVN + voff + ld0;
#pragma unroll
            for (int q = 0; q < 8; q++) {
                const int d = ld0 + q * 4;
                const int ks = d >> 3, colhi = (d >> 2) & 1;
                const float4 vk = *(const float4*)(srck + q * 4);
                const int ik = ((knb * 8 + ks) * 32 + kgr * 4) * 2 + colhi;
                Kf[ik    ] = f2tf(vk.x);
                Kf[ik + 2] = f2tf(vk.y);
                Kf[ik + 4] = f2tf(vk.z);
                Kf[ik + 6] = f2tf(vk.w);

                const int vnb = d >> 3, vgb = d & 7;
                const float4 vv = *(const float4*)(srcv + q * 4);
                const int iv = ((vnb * 8 + vks) * 32 + vgb * 4 + vgc) * 2 + vj;
                Vf[iv     ] = f2tf(vv.x);
                Vf[iv +  8] = f2tf(vv.y);
                Vf[iv + 16] = f2tf(vv.z);
                Vf[iv + 24] = f2tf(vv.w);
            }
        }
        __syncthreads();

        float sacc[8][4] = {};
#pragma unroll
        for (int ks = 0; ks < 8; ks++) {
            const uint4 av = QfU[(wid * 8 + ks) * 32 + lane];
#pragma unroll
            for (int nf = 0; nf < 8; nf++) {
                const uint2 bv = KfU[(nf * 8 + ks) * 32 + lane];
                mma_tf32(sacc[nf], av, bv);
            }
        }

        float mlo = -INFINITY, mhi = -INFINITY;
#pragma unroll
        for (int nf = 0; nf < 8; nf++) {
            mlo = fmaxf(mlo, fmaxf(sacc[nf][0], sacc[nf][1]));
            mhi = fmaxf(mhi, fmaxf(sacc[nf][2], sacc[nf][3]));
        }
#pragma unroll
        for (int o = 1; o <= 2; o <<= 1) {
            mlo = fmaxf(mlo, __shfl_xor_sync(0xffffffffu, mlo, o));
            mhi = fmaxf(mhi, __shfl_xor_sync(0xffffffffu, mhi, o));
        }
        const float mnlo = fmaxf(m_run[0], mlo);
        const float mnhi = fmaxf(m_run[1], mhi);
        const float flo  = __expf(m_run[0] - mnlo);
        const float fhi  = __expf(m_run[1] - mnhi);
        m_run[0] = mnlo; m_run[1] = mnhi;

        float rslo = 0.f, rshi = 0.f;
        const int cc = 2 * gc;
        const int pbase = ((wid * 8) * 32 + gr * 4 + (cc & 3)) * 4 + 2 * ((cc >> 2) & 1);
#pragma unroll
        for (int nf = 0; nf < 8; nf++) {
            float p0 = __expf(sacc[nf][0] - mnlo);
            float p1 = __expf(sacc[nf][1] - mnlo);
            float p2 = __expf(sacc[nf][2] - mnhi);
            float p3 = __expf(sacc[nf][3] - mnhi);
            rslo += p0 + p1;
            rshi += p2 + p3;
            const int ip = pbase + nf * 128;
            Pf[ip    ] = f2tf(p0);
            Pf[ip + 4] = f2tf(p1);
            Pf[ip + 1] = f2tf(p2);
            Pf[ip + 5] = f2tf(p3);
        }
#pragma unroll
        for (int o = 1; o <= 2; o <<= 1) {
            rslo += __shfl_xor_sync(0xffffffffu, rslo, o);
            rshi += __shfl_xor_sync(0xffffffffu, rshi, o);
        }
        l_run[0] = l_run[0] * flo + rslo;
        l_run[1] = l_run[1] * fhi + rshi;
#pragma unroll
        for (int nd = 0; nd < 8; nd++) {
            oacc[nd][0] *= flo; oacc[nd][1] *= flo;
            oacc[nd][2] *= fhi; oacc[nd][3] *= fhi;
        }
        __syncwarp();

#pragma unroll
        for (int ksv = 0; ksv < 8; ksv++) {
            const uint4 av = PfU[(wid * 8 + ksv) * 32 + lane];
#pragma unroll
            for (int nd = 0; nd < 8; nd++) {
                const uint2 bv = VfU[(nd * 8 + ksv) * 32 + lane];
                mma_tf32(oacc[nd], av, bv);
            }
        }
    }

    const float invlo = 1.0f / l_run[0];
    const float invhi = 1.0f / l_run[1];
    const int row_lo = qbase + wid * 16 + gr;
#pragma unroll
    for (int nd = 0; nd < 8; nd++) {
        const int col = h * HDIM + nd * 8 + 2 * gc;
        float2 v0, v1;
        v0.x = oacc[nd][0] * invlo; v0.y = oacc[nd][1] * invlo;
        v1.x = oacc[nd][2] * invhi; v1.y = oacc[nd][3] * invhi;
        *(float2*)&g_ctx[(size_t)row_lo * DMODEL + col]       = v0;
        *(float2*)&g_ctx[(size_t)(row_lo + 8) * DMODEL + col] = v1;
    }
}

// ---------------------------------------------------------------------------
extern "C" void kernel_launch(void* const* d_in, const int* in_sizes, int n_in,
                              void* d_out, int out_size)
{
    const float* x      = (const float*)d_in[0];
    const float* gamma  = (const float*)d_in[1];
    const float* beta   = (const float*)d_in[2];
    const float* w_qkv  = (const float*)d_in[3];
    const float* w_out  = (const float*)d_in[4];
    const float* b_out  = (const float*)d_in[5];
    float* out = (float*)d_out;

    static float* xn  = nullptr;
    static float* qkv = nullptr;
    static float* ctx = nullptr;
    static bool init = false;
    if (!init) {
        cudaGetSymbolAddress((void**)&xn,  g_xn);
        cudaGetSymbolAddress((void**)&qkv, g_qkv);
        cudaGetSymbolAddress((void**)&ctx, g_ctx);
        cudaFuncSetAttribute(attn_kernel, cudaFuncAttributeMaxDynamicSharedMemorySize, ATTN_SMEM);
        cudaFuncSetAttribute(gemm_v3_tn<false>, cudaFuncAttributeMaxDynamicSharedMemorySize, GV_SMEM);
        cudaFuncSetAttribute(gemm_v3_tn<true>,  cudaFuncAttributeMaxDynamicSharedMemorySize, GV_SMEM);
        init = true;
    }

    // 1) LayerNorm
    ln_kernel<<<MTOT, 256>>>(x, gamma, beta);

    // 2) QKV projection: [8192,1024] x [3072,1024]^T -> [8192,3072]
    gemm_v3_tn<false><<<dim3(QKVN / 128, MTOT / 128), 128, GV_SMEM>>>(xn, w_qkv, nullptr, qkv, QKVN, DMODEL);

    // 3) Attention (tf32 MMA flash)
    attn_kernel<<<dim3(SEQ / 64, BATCH * NHEAD), 128, ATTN_SMEM>>>();

    // 4) Output projection + bias: [8192,1024] x [1024,1024]^T -> [8192,1024]
    gemm_v3_tn<true><<<dim3(DMODEL / 128, MTOT / 128), 128, GV_SMEM>>>(ctx, w_out, b_out, out, DMODEL, DMODEL);
}

// round 13
// speedup vs baseline: 2.4554x; 1.3198x over previous
#include <cuda_runtime.h>
#include <math.h>
#include <stdint.h>

#define BATCH  4
#define SEQ    2048
#define DMODEL 1024
#define NHEAD  16
#define HDIM   64
#define MTOT   (BATCH * SEQ)     // 8192
#define QKVN   (3 * DMODEL)      // 3072

// Scratch (device-global statics: allocation-free per harness rules)
static __device__ float g_xn [MTOT * DMODEL];   // 32 MB
static __device__ float g_qkv[MTOT * QKVN];     // 96 MB
static __device__ float g_ctx[MTOT * DMODEL];   // 32 MB

// ---------------------------------------------------------------------------
// TF32 helpers
// ---------------------------------------------------------------------------
__device__ __forceinline__ unsigned f2tf(float x)
{
    unsigned u;
    asm("cvt.rna.tf32.f32 %0, %1;" : "=r"(u) : "f"(x));
    return u;
}

__device__ __forceinline__ void mma_tf32(float* c, const uint4& a, const uint2& b)
{
    asm volatile("mma.sync.aligned.m16n8k8.row.col.f32.tf32.tf32.f32 "
                 "{%0,%1,%2,%3}, {%4,%5,%6,%7}, {%8,%9}, {%0,%1,%2,%3};\n"
                 : "+f"(c[0]), "+f"(c[1]), "+f"(c[2]), "+f"(c[3])
                 : "r"(a.x), "r"(a.y), "r"(a.z), "r"(a.w),
                   "r"(b.x), "r"(b.y));
}

// ---------------------------------------------------------------------------
// LayerNorm: one block per row (D=1024), 256 threads, float4 per thread
// ---------------------------------------------------------------------------
__global__ __launch_bounds__(256) void ln_kernel(const float* __restrict__ x,
                                                 const float* __restrict__ gamma,
                                                 const float* __restrict__ beta)
{
    const int row = blockIdx.x;
    const int tid = threadIdx.x;
    const float4 v = ((const float4*)(x + (size_t)row * DMODEL))[tid];

    float s  = v.x + v.y + v.z + v.w;
    float s2 = v.x * v.x + v.y * v.y + v.z * v.z + v.w * v.w;
#pragma unroll
    for (int o = 16; o > 0; o >>= 1) {
        s  += __shfl_xor_sync(0xffffffffu, s,  o);
        s2 += __shfl_xor_sync(0xffffffffu, s2, o);
    }
    __shared__ float rs[8], rs2[8], mv[2];
    if ((tid & 31) == 0) { rs[tid >> 5] = s; rs2[tid >> 5] = s2; }
    __syncthreads();
    if (tid == 0) {
        float a = 0.f, b2 = 0.f;
#pragma unroll
        for (int i = 0; i < 8; i++) { a += rs[i]; b2 += rs2[i]; }
        const float mean = a * (1.0f / DMODEL);
        const float var  = b2 * (1.0f / DMODEL) - mean * mean;
        mv[0] = mean;
        mv[1] = rsqrtf(var + 1e-5f);
    }
    __syncthreads();
    const float mean = mv[0], r = mv[1];
    const float4 g  = ((const float4*)gamma)[tid];
    const float4 be = ((const float4*)beta)[tid];
    float4 o;
    o.x = (v.x - mean) * r * g.x + be.x;
    o.y = (v.y - mean) * r * g.y + be.y;
    o.z = (v.z - mean) * r * g.z + be.z;
    o.w = (v.w - mean) * r * g.w + be.w;
    ((float4*)(g_xn + (size_t)row * DMODEL))[tid] = o;
}

// ===========================================================================
// TF32 MMA GEMM v3 (unchanged from round 12 — validated):
// CTA 128x128x32, 128 threads = 4 warps, warp tile 64x64, j-outer planes.
// ===========================================================================
#define GV_APLANE  1028
#define GV_BPLANE  2052
#define GV_AREG    (4 * GV_APLANE)
#define GV_STAGE   (GV_AREG + 2 * GV_BPLANE)
#define GV_SMEM    (2 * GV_STAGE * 4)

template <bool HAS_BIAS>
__global__ __launch_bounds__(128, 2) void gemm_v3_tn(const float* __restrict__ A,
                                                     const float* __restrict__ Bm,
                                                     const float* __restrict__ bias,
                                                     float* __restrict__ C,
                                                     int N, int K)
{
    extern __shared__ unsigned sw[];

    const int tid  = threadIdx.x;
    const int lane = tid & 31;
    const int wid  = tid >> 5;
    const int wm   = wid >> 1;
    const int wn   = wid & 1;
    const int bm   = blockIdx.y * 128;
    const int bn   = blockIdx.x * 128;

    const float* Ap = A  + (size_t)(bm + tid) * K;
    const float* Bp = Bm + (size_t)(bn + tid) * K;

    int aoffw[8], boffw[8];
    {
        const int mbA = tid >> 4, arr = tid & 15, agr = arr & 7, rowhi = arr >> 3;
        const int nbB = tid >> 3, bgr = tid & 7;
#pragma unroll
        for (int q = 0; q < 8; q++) {
            const int ks = q >> 1, chi = q & 1;
            aoffw[q] = (rowhi + 2 * chi) * GV_APLANE + (mbA * 4 + ks) * 32 + agr * 4;
            boffw[q] = GV_AREG + chi * GV_BPLANE + (nbB * 4 + ks) * 32 + bgr * 4;
        }
    }

    float acc[4][8][4] = {};
    const int nc = K >> 5;

    {
        float4 av[8], bv[8];
#pragma unroll
        for (int q = 0; q < 8; q++) { av[q] = *(const float4*)(Ap + q * 4);
                                      bv[q] = *(const float4*)(Bp + q * 4); }
#pragma unroll
        for (int q = 0; q < 8; q++) {
            *(uint4*)(sw + aoffw[q]) = make_uint4(f2tf(av[q].x), f2tf(av[q].y),
                                                  f2tf(av[q].z), f2tf(av[q].w));
            *(uint4*)(sw + boffw[q]) = make_uint4(f2tf(bv[q].x), f2tf(bv[q].y),
                                                  f2tf(bv[q].z), f2tf(bv[q].w));
        }
    }
    __syncthreads();

    for (int c = 0; c < nc; c++) {
        const bool more = (c + 1 < nc);
        float4 av[8], bv[8];
        if (more) {
            const int kc = (c + 1) * 32;
#pragma unroll
            for (int q = 0; q < 8; q++) { av[q] = *(const float4*)(Ap + kc + q * 4);
                                          bv[q] = *(const float4*)(Bp + kc + q * 4); }
        }

        const unsigned* bufc = sw + (c & 1) * GV_STAGE;
#pragma unroll
        for (int ks = 0; ks < 4; ks++) {
            uint4 a[4];
            uint2 b[8];
#pragma unroll
            for (int mi = 0; mi < 4; mi++) {
                const int base = ((wm * 4 + mi) * 4 + ks) * 32 + lane;
                a[mi] = make_uint4(bufc[base],
                                   bufc[GV_APLANE     + base],
                                   bufc[2 * GV_APLANE + base],
                                   bufc[3 * GV_APLANE + base]);
            }
#pragma unroll
            for (int ni = 0; ni < 8; ni++) {
                const int base = GV_AREG + ((wn * 8 + ni) * 4 + ks) * 32 + lane;
                b[ni] = make_uint2(bufc[base], bufc[GV_BPLANE + base]);
            }
#pragma unroll
            for (int mi = 0; mi < 4; mi++)
#pragma unroll
                for (int ni = 0; ni < 8; ni++)
                    mma_tf32(acc[mi][ni], a[mi], b[ni]);
        }

        if (more) {
            unsigned* bufn = sw + ((c + 1) & 1) * GV_STAGE;
#pragma unroll
            for (int q = 0; q < 8; q++) {
                *(uint4*)(bufn + aoffw[q]) = make_uint4(f2tf(av[q].x), f2tf(av[q].y),
                                                        f2tf(av[q].z), f2tf(av[q].w));
                *(uint4*)(bufn + boffw[q]) = make_uint4(f2tf(bv[q].x), f2tf(bv[q].y),
                                                        f2tf(bv[q].z), f2tf(bv[q].w));
            }
        }
        __syncthreads();
    }

    const int gr = lane >> 2, gc = lane & 3;
#pragma unroll
    for (int mi = 0; mi < 4; mi++) {
        const int row0 = bm + wm * 64 + mi * 16 + gr;
#pragma unroll
        for (int ni = 0; ni < 8; ni++) {
            const int col = bn + wn * 64 + ni * 8 + 2 * gc;
            float b0 = 0.f, b1 = 0.f;
            if (HAS_BIAS) { b0 = bias[col]; b1 = bias[col + 1]; }
            float2 v0, v1;
            v0.x = acc[mi][ni][0] + b0; v0.y = acc[mi][ni][1] + b1;
            v1.x = acc[mi][ni][2] + b0; v1.y = acc[mi][ni][3] + b1;
            *(float2*)&C[(size_t)row0 * N + col]       = v0;
            *(float2*)&C[(size_t)(row0 + 8) * N + col] = v1;
        }
    }
}

// ---------------------------------------------------------------------------
// TF32 MMA flash attention v2: CTA = 128 q-rows of one (b,h); 256 threads
// (8 warps), warp w owns q-rows [w*16, w*16+16). kv chunks of 64.
// Smem (96 KB): Qf[8mb][8ks][32][4] 32KB | Kf 16KB | Vf 16KB | Pf 32KB
// Per-warp math identical to round-10 kernel (validated); K/V load + scatter
// amortized over 2x q-rows.
// ---------------------------------------------------------------------------
#define ATTN_SMEM (24576 * 4)

__global__ __launch_bounds__(256, 2) void attn_kernel()
{
    extern __shared__ unsigned fr[];
    unsigned* Qf = fr;              // 8192 w
    unsigned* Kf = fr + 8192;       // 4096 w
    unsigned* Vf = fr + 12288;      // 4096 w
    unsigned* Pf = fr + 16384;      // 8192 w

    const int qt   = blockIdx.x;
    const int bh   = blockIdx.y;
    const int b    = bh >> 4;
    const int h    = bh & 15;
    const int tid  = threadIdx.x;
    const int lane = tid & 31;
    const int wid  = tid >> 5;      // 0..7
    const int gr   = lane >> 2;
    const int gc   = lane & 3;

    const int qoff  = h * HDIM;
    const int koff  = DMODEL + h * HDIM;
    const int voff  = 2 * DMODEL + h * HDIM;
    const int qbase = b * SEQ + qt * 128;
    const int kvbas = b * SEQ;

    // ---- load Q once (scale 1/8 folded): 128 rows, thread owns half-row
    {
        const int lrow = tid >> 1;            // 0..127
        const int ld0  = (tid & 1) * 32;
        const int mb = lrow >> 4, rr = lrow & 15, qgr = rr & 7, rowhi = rr >> 3;
        const float* src = g_qkv + (size_t)(qbase + lrow) * QKVN + qoff + ld0;
#pragma unroll
        for (int q = 0; q < 8; q++) {
            const int d = ld0 + q * 4;
            const int ks = d >> 3, colhi = (d >> 2) & 1;
            const float4 v = *(const float4*)(src + q * 4);
            const int i0 = ((mb * 8 + ks) * 32 + qgr * 4) * 4 + rowhi + 2 * colhi;
            Qf[i0     ] = f2tf(v.x * 0.125f);
            Qf[i0 +  4] = f2tf(v.y * 0.125f);
            Qf[i0 +  8] = f2tf(v.z * 0.125f);
            Qf[i0 + 12] = f2tf(v.w * 0.125f);
        }
    }

    float m_run[2] = {-INFINITY, -INFINITY};
    float l_run[2] = {0.f, 0.f};
    float oacc[8][4] = {};

    const uint4* QfU = (const uint4*)Qf;
    const uint2* KfU = (const uint2*)Kf;
    const uint2* VfU = (const uint2*)Vf;
    const uint4* PfU = (const uint4*)Pf;

    // K/V loader geometry: 64 rows, thread owns quarter-row (16 floats)
    const int kvrow = tid >> 2;           // 0..63
    const int kld0  = (tid & 3) * 16;     // 0,16,32,48

    for (int kt = 0; kt < SEQ / 64; kt++) {
        __syncthreads();   // previous chunk's MMAs done before overwriting K/V

        {
            const int kv  = kvrow;
            const int knb = kv >> 3, kgr = kv & 7;
            const int vks = kv >> 3, vgc = kv & 3, vj = (kv >> 2) & 1;
            const float* srck = g_qkv + (size_t)(kvbas + kt * 64 + kv) * QKVN + koff + kld0;
            const float* srcv = g_qkv + (size_t)(kvbas + kt * 64 + kv) * QKVN + voff + kld0;
#pragma unroll
            for (int q = 0; q < 4; q++) {
                const int d = kld0 + q * 4;
                const int ks = d >> 3, colhi = (d >> 2) & 1;
                const float4 vk = *(const float4*)(srck + q * 4);
                const int ik = ((knb * 8 + ks) * 32 + kgr * 4) * 2 + colhi;
                Kf[ik    ] = f2tf(vk.x);
                Kf[ik + 2] = f2tf(vk.y);
                Kf[ik + 4] = f2tf(vk.z);
                Kf[ik + 6] = f2tf(vk.w);

                const int vnb = d >> 3, vgb = d & 7;
                const float4 vv = *(const float4*)(srcv + q * 4);
                const int iv = ((vnb * 8 + vks) * 32 + vgb * 4 + vgc) * 2 + vj;
                Vf[iv     ] = f2tf(vv.x);
                Vf[iv +  8] = f2tf(vv.y);
                Vf[iv + 16] = f2tf(vv.z);
                Vf[iv + 24] = f2tf(vv.w);
            }
        }
        __syncthreads();

        // ---- S = Q K^T (warp: 16 x 64 over d=64)
        float sacc[8][4] = {};
#pragma unroll
        for (int ks = 0; ks < 8; ks++) {
            const uint4 av = QfU[(wid * 8 + ks) * 32 + lane];
#pragma unroll
            for (int nf = 0; nf < 8; nf++) {
                const uint2 bv = KfU[(nf * 8 + ks) * 32 + lane];
                mma_tf32(sacc[nf], av, bv);
            }
        }

        // ---- online softmax on C-frags (rows gr, gr+8)
        float mlo = -INFINITY, mhi = -INFINITY;
#pragma unroll
        for (int nf = 0; nf < 8; nf++) {
            mlo = fmaxf(mlo, fmaxf(sacc[nf][0], sacc[nf][1]));
            mhi = fmaxf(mhi, fmaxf(sacc[nf][2], sacc[nf][3]));
        }
#pragma unroll
        for (int o = 1; o <= 2; o <<= 1) {
            mlo = fmaxf(mlo, __shfl_xor_sync(0xffffffffu, mlo, o));
            mhi = fmaxf(mhi, __shfl_xor_sync(0xffffffffu, mhi, o));
        }
        const float mnlo = fmaxf(m_run[0], mlo);
        const float mnhi = fmaxf(m_run[1], mhi);
        const float flo  = __expf(m_run[0] - mnlo);
        const float fhi  = __expf(m_run[1] - mnhi);
        m_run[0] = mnlo; m_run[1] = mnhi;

        float rslo = 0.f, rshi = 0.f;
        const int cc = 2 * gc;
        const int pbase = ((wid * 8) * 32 + gr * 4 + (cc & 3)) * 4 + 2 * ((cc >> 2) & 1);
#pragma unroll
        for (int nf = 0; nf < 8; nf++) {
            float p0 = __expf(sacc[nf][0] - mnlo);
            float p1 = __expf(sacc[nf][1] - mnlo);
            float p2 = __expf(sacc[nf][2] - mnhi);
            float p3 = __expf(sacc[nf][3] - mnhi);
            rslo += p0 + p1;
            rshi += p2 + p3;
            const int ip = pbase + nf * 128;
            Pf[ip    ] = f2tf(p0);
            Pf[ip + 4] = f2tf(p1);
            Pf[ip + 1] = f2tf(p2);
            Pf[ip + 5] = f2tf(p3);
        }
#pragma unroll
        for (int o = 1; o <= 2; o <<= 1) {
            rslo += __shfl_xor_sync(0xffffffffu, rslo, o);
            rshi += __shfl_xor_sync(0xffffffffu, rshi, o);
        }
        l_run[0] = l_run[0] * flo + rslo;
        l_run[1] = l_run[1] * fhi + rshi;
#pragma unroll
        for (int nd = 0; nd < 8; nd++) {
            oacc[nd][0] *= flo; oacc[nd][1] *= flo;
            oacc[nd][2] *= fhi; oacc[nd][3] *= fhi;
        }
        __syncwarp();   // Pf region is warp-private

        // ---- O += P V (warp: 16 x 64 over kv=64)
#pragma unroll
        for (int ksv = 0; ksv < 8; ksv++) {
            const uint4 av = PfU[(wid * 8 + ksv) * 32 + lane];
#pragma unroll
            for (int nd = 0; nd < 8; nd++) {
                const uint2 bv = VfU[(nd * 8 + ksv) * 32 + lane];
                mma_tf32(oacc[nd], av, bv);
            }
        }
    }

    // ---- normalize + write ctx
    const float invlo = 1.0f / l_run[0];
    const float invhi = 1.0f / l_run[1];
    const int row_lo = qbase + wid * 16 + gr;
#pragma unroll
    for (int nd = 0; nd < 8; nd++) {
        const int col = h * HDIM + nd * 8 + 2 * gc;
        float2 v0, v1;
        v0.x = oacc[nd][0] * invlo; v0.y = oacc[nd][1] * invlo;
        v1.x = oacc[nd][2] * invhi; v1.y = oacc[nd][3] * invhi;
        *(float2*)&g_ctx[(size_t)row_lo * DMODEL + col]       = v0;
        *(float2*)&g_ctx[(size_t)(row_lo + 8) * DMODEL + col] = v1;
    }
}

// ---------------------------------------------------------------------------
extern "C" void kernel_launch(void* const* d_in, const int* in_sizes, int n_in,
                              void* d_out, int out_size)
{
    const float* x      = (const float*)d_in[0];
    const float* gamma  = (const float*)d_in[1];
    const float* beta   = (const float*)d_in[2];
    const float* w_qkv  = (const float*)d_in[3];
    const float* w_out  = (const float*)d_in[4];
    const float* b_out  = (const float*)d_in[5];
    float* out = (float*)d_out;

    static float* xn  = nullptr;
    static float* qkv = nullptr;
    static float* ctx = nullptr;
    static bool init = false;
    if (!init) {
        cudaGetSymbolAddress((void**)&xn,  g_xn);
        cudaGetSymbolAddress((void**)&qkv, g_qkv);
        cudaGetSymbolAddress((void**)&ctx, g_ctx);
        cudaFuncSetAttribute(attn_kernel, cudaFuncAttributeMaxDynamicSharedMemorySize, ATTN_SMEM);
        cudaFuncSetAttribute(gemm_v3_tn<false>, cudaFuncAttributeMaxDynamicSharedMemorySize, GV_SMEM);
        cudaFuncSetAttribute(gemm_v3_tn<true>,  cudaFuncAttributeMaxDynamicSharedMemorySize, GV_SMEM);
        init = true;
    }

    // 1) LayerNorm
    ln_kernel<<<MTOT, 256>>>(x, gamma, beta);

    // 2) QKV projection: [8192,1024] x [3072,1024]^T -> [8192,3072]
    gemm_v3_tn<false><<<dim3(QKVN / 128, MTOT / 128), 128, GV_SMEM>>>(xn, w_qkv, nullptr, qkv, QKVN, DMODEL);

    // 3) Attention (tf32 MMA flash, 128-q tiles)
    attn_kernel<<<dim3(SEQ / 128, BATCH * NHEAD), 256, ATTN_SMEM>>>();

    // 4) Output projection + bias: [8192,1024] x [1024,1024]^T -> [8192,1024]
    gemm_v3_tn<true><<<dim3(DMODEL / 128, MTOT / 128), 128, GV_SMEM>>>(ctx, w_out, b_out, out, DMODEL, DMODEL);
}

// round 14
// speedup vs baseline: 2.7481x; 1.1192x over previous
#include <cuda_runtime.h>
#include <math.h>
#include <stdint.h>

#define BATCH  4
#define SEQ    2048
#define DMODEL 1024
#define NHEAD  16
#define HDIM   64
#define MTOT   (BATCH * SEQ)     // 8192
#define QKVN   (3 * DMODEL)      // 3072

// Scratch (device-global statics: allocation-free per harness rules)
static __device__ float g_xn [MTOT * DMODEL];   // 32 MB
static __device__ float g_qkv[MTOT * QKVN];     // 96 MB
static __device__ float g_ctx[MTOT * DMODEL];   // 32 MB

// ---------------------------------------------------------------------------
// TF32 helpers
// ---------------------------------------------------------------------------
__device__ __forceinline__ unsigned f2tf(float x)
{
    unsigned u;
    asm("cvt.rna.tf32.f32 %0, %1;" : "=r"(u) : "f"(x));
    return u;
}

__device__ __forceinline__ void mma_tf32(float* c, const uint4& a, const uint2& b)
{
    asm volatile("mma.sync.aligned.m16n8k8.row.col.f32.tf32.tf32.f32 "
                 "{%0,%1,%2,%3}, {%4,%5,%6,%7}, {%8,%9}, {%0,%1,%2,%3};\n"
                 : "+f"(c[0]), "+f"(c[1]), "+f"(c[2]), "+f"(c[3])
                 : "r"(a.x), "r"(a.y), "r"(a.z), "r"(a.w),
                   "r"(b.x), "r"(b.y));
}

// ---------------------------------------------------------------------------
// LayerNorm: one block per row (D=1024), 256 threads, float4 per thread
// ---------------------------------------------------------------------------
__global__ __launch_bounds__(256) void ln_kernel(const float* __restrict__ x,
                                                 const float* __restrict__ gamma,
                                                 const float* __restrict__ beta)
{
    const int row = blockIdx.x;
    const int tid = threadIdx.x;
    const float4 v = ((const float4*)(x + (size_t)row * DMODEL))[tid];

    float s  = v.x + v.y + v.z + v.w;
    float s2 = v.x * v.x + v.y * v.y + v.z * v.z + v.w * v.w;
#pragma unroll
    for (int o = 16; o > 0; o >>= 1) {
        s  += __shfl_xor_sync(0xffffffffu, s,  o);
        s2 += __shfl_xor_sync(0xffffffffu, s2, o);
    }
    __shared__ float rs[8], rs2[8], mv[2];
    if ((tid & 31) == 0) { rs[tid >> 5] = s; rs2[tid >> 5] = s2; }
    __syncthreads();
    if (tid == 0) {
        float a = 0.f, b2 = 0.f;
#pragma unroll
        for (int i = 0; i < 8; i++) { a += rs[i]; b2 += rs2[i]; }
        const float mean = a * (1.0f / DMODEL);
        const float var  = b2 * (1.0f / DMODEL) - mean * mean;
        mv[0] = mean;
        mv[1] = rsqrtf(var + 1e-5f);
    }
    __syncthreads();
    const float mean = mv[0], r = mv[1];
    const float4 g  = ((const float4*)gamma)[tid];
    const float4 be = ((const float4*)beta)[tid];
    float4 o;
    o.x = (v.x - mean) * r * g.x + be.x;
    o.y = (v.y - mean) * r * g.y + be.y;
    o.z = (v.z - mean) * r * g.z + be.z;
    o.w = (v.w - mean) * r * g.w + be.w;
    ((float4*)(g_xn + (size_t)row * DMODEL))[tid] = o;
}

// ===========================================================================
// TF32 MMA GEMM v4: C[m,n] = sum_k A[m,k]*B[n,k] (+bias[n])
// CTA 128x128x32, 256 threads = 8 warps (wm 0..1 x wn 0..3), warp tile 64x32.
// Same j-outer plane fragment layout as v3 (validated). Loader: thread owns
// half-row (16 k-floats = 4 float4) of A and of B.
// ===========================================================================
#define GV_APLANE  1028
#define GV_BPLANE  2052
#define GV_AREG    (4 * GV_APLANE)
#define GV_STAGE   (GV_AREG + 2 * GV_BPLANE)
#define GV_SMEM    (2 * GV_STAGE * 4)

template <bool HAS_BIAS>
__global__ __launch_bounds__(256, 2) void gemm_v4_tn(const float* __restrict__ A,
                                                     const float* __restrict__ Bm,
                                                     const float* __restrict__ bias,
                                                     float* __restrict__ C,
                                                     int N, int K)
{
    extern __shared__ unsigned sw[];

    const int tid  = threadIdx.x;
    const int lane = tid & 31;
    const int wid  = tid >> 5;          // 0..7
    const int wm   = wid >> 2;          // 0..1
    const int wn   = wid & 3;           // 0..3
    const int bm   = blockIdx.y * 128;
    const int bn   = blockIdx.x * 128;

    // ---- loader: thread owns half-row (row = tid>>1, k-half = tid&1)
    const int arow = tid >> 1;
    const int ak0  = (tid & 1) * 16;
    const float* Ap = A  + (size_t)(bm + arow) * K + ak0;
    const float* Bp = Bm + (size_t)(bn + arow) * K + ak0;

    int aoffw[4], boffw[4];
    {
        const int mbA = arow >> 4, arr = arow & 15, agr = arr & 7, rowhi = arr >> 3;
        const int nbB = arow >> 3, bgr = arow & 7;
#pragma unroll
        for (int q = 0; q < 4; q++) {
            const int k0 = ak0 + q * 4;
            const int ks = k0 >> 3, chi = (k0 >> 2) & 1;
            aoffw[q] = (rowhi + 2 * chi) * GV_APLANE + (mbA * 4 + ks) * 32 + agr * 4;
            boffw[q] = GV_AREG + chi * GV_BPLANE + (nbB * 4 + ks) * 32 + bgr * 4;
        }
    }

    float acc[4][4][4] = {};
    const int nc = K >> 5;

    // ---- prologue: chunk 0 -> stage 0
    {
        float4 av[4], bv[4];
#pragma unroll
        for (int q = 0; q < 4; q++) { av[q] = *(const float4*)(Ap + q * 4);
                                      bv[q] = *(const float4*)(Bp + q * 4); }
#pragma unroll
        for (int q = 0; q < 4; q++) {
            *(uint4*)(sw + aoffw[q]) = make_uint4(f2tf(av[q].x), f2tf(av[q].y),
                                                  f2tf(av[q].z), f2tf(av[q].w));
            *(uint4*)(sw + boffw[q]) = make_uint4(f2tf(bv[q].x), f2tf(bv[q].y),
                                                  f2tf(bv[q].z), f2tf(bv[q].w));
        }
    }
    __syncthreads();

    for (int c = 0; c < nc; c++) {
        const bool more = (c + 1 < nc);
        float4 av[4], bv[4];
        if (more) {
            const int kc = (c + 1) * 32;
#pragma unroll
            for (int q = 0; q < 4; q++) { av[q] = *(const float4*)(Ap + kc + q * 4);
                                          bv[q] = *(const float4*)(Bp + kc + q * 4); }
        }

        // ---- MMA on current stage (prefetch LDGs drain underneath)
        const unsigned* bufc = sw + (c & 1) * GV_STAGE;
#pragma unroll
        for (int ks = 0; ks < 4; ks++) {
            uint4 a[4];
            uint2 b[4];
#pragma unroll
            for (int mi = 0; mi < 4; mi++) {
                const int base = ((wm * 4 + mi) * 4 + ks) * 32 + lane;
                a[mi] = make_uint4(bufc[base],
                                   bufc[GV_APLANE     + base],
                                   bufc[2 * GV_APLANE + base],
                                   bufc[3 * GV_APLANE + base]);
            }
#pragma unroll
            for (int ni = 0; ni < 4; ni++) {
                const int base = GV_AREG + ((wn * 4 + ni) * 4 + ks) * 32 + lane;
                b[ni] = make_uint2(bufc[base], bufc[GV_BPLANE + base]);
            }
#pragma unroll
            for (int mi = 0; mi < 4; mi++)
#pragma unroll
                for (int ni = 0; ni < 4; ni++)
                    mma_tf32(acc[mi][ni], a[mi], b[ni]);
        }

        // ---- store prefetched chunk into other stage
        if (more) {
            unsigned* bufn = sw + ((c + 1) & 1) * GV_STAGE;
#pragma unroll
            for (int q = 0; q < 4; q++) {
                *(uint4*)(bufn + aoffw[q]) = make_uint4(f2tf(av[q].x), f2tf(av[q].y),
                                                        f2tf(av[q].z), f2tf(av[q].w));
                *(uint4*)(bufn + boffw[q]) = make_uint4(f2tf(bv[q].x), f2tf(bv[q].y),
                                                        f2tf(bv[q].z), f2tf(bv[q].w));
            }
        }
        __syncthreads();
    }

    // ---- epilogue
    const int gr = lane >> 2, gc = lane & 3;
#pragma unroll
    for (int mi = 0; mi < 4; mi++) {
        const int row0 = bm + wm * 64 + mi * 16 + gr;
#pragma unroll
        for (int ni = 0; ni < 4; ni++) {
            const int col = bn + wn * 32 + ni * 8 + 2 * gc;
            float b0 = 0.f, b1 = 0.f;
            if (HAS_BIAS) { b0 = bias[col]; b1 = bias[col + 1]; }
            float2 v0, v1;
            v0.x = acc[mi][ni][0] + b0; v0.y = acc[mi][ni][1] + b1;
            v1.x = acc[mi][ni][2] + b0; v1.y = acc[mi][ni][3] + b1;
            *(float2*)&C[(size_t)row0 * N + col]       = v0;
            *(float2*)&C[(size_t)(row0 + 8) * N + col] = v1;
        }
    }
}

// ---------------------------------------------------------------------------
// TF32 MMA flash attention v3: CTA = 128 q-rows of one (b,h); 256 threads
// (8 warps). kv chunks of 64, K/V register-prefetched one chunk ahead so the
// global-load latency drains under MMA+softmax.
// Smem (96 KB): Qf 32KB | Kf 16KB | Vf 16KB | Pf 32KB
// ---------------------------------------------------------------------------
#define ATTN_SMEM (24576 * 4)

__global__ __launch_bounds__(256, 2) void attn_kernel()
{
    extern __shared__ unsigned fr[];
    unsigned* Qf = fr;              // 8192 w
    unsigned* Kf = fr + 8192;       // 4096 w
    unsigned* Vf = fr + 12288;      // 4096 w
    unsigned* Pf = fr + 16384;      // 8192 w

    const int qt   = blockIdx.x;
    const int bh   = blockIdx.y;
    const int b    = bh >> 4;
    const int h    = bh & 15;
    const int tid  = threadIdx.x;
    const int lane = tid & 31;
    const int wid  = tid >> 5;      // 0..7
    const int gr   = lane >> 2;
    const int gc   = lane & 3;

    const int qoff  = h * HDIM;
    const int koff  = DMODEL + h * HDIM;
    const int voff  = 2 * DMODEL + h * HDIM;
    const int qbase = b * SEQ + qt * 128;
    const int kvbas = b * SEQ;

    // ---- load Q once (scale 1/8 folded): 128 rows, thread owns half-row
    {
        const int lrow = tid >> 1;            // 0..127
        const int ld0  = (tid & 1) * 32;
        const int mb = lrow >> 4, rr = lrow & 15, qgr = rr & 7, rowhi = rr >> 3;
        const float* src = g_qkv + (size_t)(qbase + lrow) * QKVN + qoff + ld0;
#pragma unroll
        for (int q = 0; q < 8; q++) {
            const int d = ld0 + q * 4;
            const int ks = d >> 3, colhi = (d >> 2) & 1;
            const float4 v = *(const float4*)(src + q * 4);
            const int i0 = ((mb * 8 + ks) * 32 + qgr * 4) * 4 + rowhi + 2 * colhi;
            Qf[i0     ] = f2tf(v.x * 0.125f);
            Qf[i0 +  4] = f2tf(v.y * 0.125f);
            Qf[i0 +  8] = f2tf(v.z * 0.125f);
            Qf[i0 + 12] = f2tf(v.w * 0.125f);
        }
    }

    float m_run[2] = {-INFINITY, -INFINITY};
    float l_run[2] = {0.f, 0.f};
    float oacc[8][4] = {};

    const uint4* QfU = (const uint4*)Qf;
    const uint2* KfU = (const uint2*)Kf;
    const uint2* VfU = (const uint2*)Vf;
    const uint4* PfU = (const uint4*)Pf;

    // K/V loader geometry: 64 rows, thread owns quarter-row (16 floats)
    const int kvrow = tid >> 2;           // 0..63
    const int kld0  = (tid & 3) * 16;     // 0,16,32,48

    // scatter offsets (precomputed once)
    int koffw[4], voffw[4];
    {
        const int kv  = kvrow;
        const int knb = kv >> 3, kgr = kv & 7;
        const int vks = kv >> 3, vgc = kv & 3, vj = (kv >> 2) & 1;
#pragma unroll
        for (int q = 0; q < 4; q++) {
            const int d = kld0 + q * 4;
            const int ks = d >> 3, colhi = (d >> 2) & 1;
            koffw[q] = ((knb * 8 + ks) * 32 + kgr * 4) * 2 + colhi;
            const int vnb = d >> 3, vgb = d & 7;
            voffw[q] = ((vnb * 8 + vks) * 32 + vgb * 4 + vgc) * 2 + vj;
        }
    }

    float4 kreg[4], vreg[4];
    // ---- prologue: fetch chunk 0 K/V into registers
    {
        const float* srck = g_qkv + (size_t)(kvbas + kvrow) * QKVN + koff + kld0;
        const float* srcv = g_qkv + (size_t)(kvbas + kvrow) * QKVN + voff + kld0;
#pragma unroll
        for (int q = 0; q < 4; q++) { kreg[q] = *(const float4*)(srck + q * 4);
                                      vreg[q] = *(const float4*)(srcv + q * 4); }
    }

    for (int kt = 0; kt < SEQ / 64; kt++) {
        __syncthreads();   // previous chunk's MMAs done before overwriting K/V

        // ---- scatter prefetched K/V registers into fragment smem
#pragma unroll
        for (int q = 0; q < 4; q++) {
            Kf[koffw[q]    ] = f2tf(kreg[q].x);
            Kf[koffw[q] + 2] = f2tf(kreg[q].y);
            Kf[koffw[q] + 4] = f2tf(kreg[q].z);
            Kf[koffw[q] + 6] = f2tf(kreg[q].w);
            Vf[voffw[q]     ] = f2tf(vreg[q].x);
            Vf[voffw[q] +  8] = f2tf(vreg[q].y);
            Vf[voffw[q] + 16] = f2tf(vreg[q].z);
            Vf[voffw[q] + 24] = f2tf(vreg[q].w);
        }
        __syncthreads();

        // ---- issue next chunk's LDGs (drain under MMA + softmax below)
        if (kt + 1 < SEQ / 64) {
            const float* srck = g_qkv + (size_t)(kvbas + (kt + 1) * 64 + kvrow) * QKVN + koff + kld0;
            const float* srcv = g_qkv + (size_t)(kvbas + (kt + 1) * 64 + kvrow) * QKVN + voff + kld0;
#pragma unroll
            for (int q = 0; q < 4; q++) { kreg[q] = *(const float4*)(srck + q * 4);
                                          vreg[q] = *(const float4*)(srcv + q * 4); }
        }

        // ---- S = Q K^T (warp: 16 x 64 over d=64)
        float sacc[8][4] = {};
#pragma unroll
        for (int ks = 0; ks < 8; ks++) {
            const uint4 av = QfU[(wid * 8 + ks) * 32 + lane];
#pragma unroll
            for (int nf = 0; nf < 8; nf++) {
                const uint2 bv = KfU[(nf * 8 + ks) * 32 + lane];
                mma_tf32(sacc[nf], av, bv);
            }
        }

        // ---- online softmax on C-frags (rows gr, gr+8)
        float mlo = -INFINITY, mhi = -INFINITY;
#pragma unroll
        for (int nf = 0; nf < 8; nf++) {
            mlo = fmaxf(mlo, fmaxf(sacc[nf][0], sacc[nf][1]));
            mhi = fmaxf(mhi, fmaxf(sacc[nf][2], sacc[nf][3]));
        }
#pragma unroll
        for (int o = 1; o <= 2; o <<= 1) {
            mlo = fmaxf(mlo, __shfl_xor_sync(0xffffffffu, mlo, o));
            mhi = fmaxf(mhi, __shfl_xor_sync(0xffffffffu, mhi, o));
        }
        const float mnlo = fmaxf(m_run[0], mlo);
        const float mnhi = fmaxf(m_run[1], mhi);
        const float flo  = __expf(m_run[0] - mnlo);
        const float fhi  = __expf(m_run[1] - mnhi);
        m_run[0] = mnlo; m_run[1] = mnhi;

        float rslo = 0.f, rshi = 0.f;
        const int cc = 2 * gc;
        const int pbase = ((wid * 8) * 32 + gr * 4 + (cc & 3)) * 4 + 2 * ((cc >> 2) & 1);
#pragma unroll
        for (int nf = 0; nf < 8; nf++) {
            float p0 = __expf(sacc[nf][0] - mnlo);
            float p1 = __expf(sacc[nf][1] - mnlo);
            float p2 = __expf(sacc[nf][2] - mnhi);
            float p3 = __expf(sacc[nf][3] - mnhi);
            rslo += p0 + p1;
            rshi += p2 + p3;
            const int ip = pbase + nf * 128;
            Pf[ip    ] = f2tf(p0);
            Pf[ip + 4] = f2tf(p1);
            Pf[ip + 1] = f2tf(p2);
            Pf[ip + 5] = f2tf(p3);
        }
#pragma unroll
        for (int o = 1; o <= 2; o <<= 1) {
            rslo += __shfl_xor_sync(0xffffffffu, rslo, o);
            rshi += __shfl_xor_sync(0xffffffffu, rshi, o);
        }
        l_run[0] = l_run[0] * flo + rslo;
        l_run[1] = l_run[1] * fhi + rshi;
#pragma unroll
        for (int nd = 0; nd < 8; nd++) {
            oacc[nd][0] *= flo; oacc[nd][1] *= flo;
            oacc[nd][2] *= fhi; oacc[nd][3] *= fhi;
        }
        __syncwarp();   // Pf region is warp-private

        // ---- O += P V (warp: 16 x 64 over kv=64)
#pragma unroll
        for (int ksv = 0; ksv < 8; ksv++) {
            const uint4 av = PfU[(wid * 8 + ksv) * 32 + lane];
#pragma unroll
            for (int nd = 0; nd < 8; nd++) {
                const uint2 bv = VfU[(nd * 8 + ksv) * 32 + lane];
                mma_tf32(oacc[nd], av, bv);
            }
        }
    }

    // ---- normalize + write ctx
    const float invlo = 1.0f / l_run[0];
    const float invhi = 1.0f / l_run[1];
    const int row_lo = qbase + wid * 16 + gr;
#pragma unroll
    for (int nd = 0; nd < 8; nd++) {
        const int col = h * HDIM + nd * 8 + 2 * gc;
        float2 v0, v1;
        v0.x = oacc[nd][0] * invlo; v0.y = oacc[nd][1] * invlo;
        v1.x = oacc[nd][2] * invhi; v1.y = oacc[nd][3] * invhi;
        *(float2*)&g_ctx[(size_t)row_lo * DMODEL + col]       = v0;
        *(float2*)&g_ctx[(size_t)(row_lo + 8) * DMODEL + col] = v1;
    }
}

// ---------------------------------------------------------------------------
extern "C" void kernel_launch(void* const* d_in, const int* in_sizes, int n_in,
                              void* d_out, int out_size)
{
    const float* x      = (const float*)d_in[0];
    const float* gamma  = (const float*)d_in[1];
    const float* beta   = (const float*)d_in[2];
    const float* w_qkv  = (const float*)d_in[3];
    const float* w_out  = (const float*)d_in[4];
    const float* b_out  = (const float*)d_in[5];
    float* out = (float*)d_out;

    static float* xn  = nullptr;
    static float* qkv = nullptr;
    static float* ctx = nullptr;
    static bool init = false;
    if (!init) {
        cudaGetSymbolAddress((void**)&xn,  g_xn);
        cudaGetSymbolAddress((void**)&qkv, g_qkv);
        cudaGetSymbolAddress((void**)&ctx, g_ctx);
        cudaFuncSetAttribute(attn_kernel, cudaFuncAttributeMaxDynamicSharedMemorySize, ATTN_SMEM);
        cudaFuncSetAttribute(gemm_v4_tn<false>, cudaFuncAttributeMaxDynamicSharedMemorySize, GV_SMEM);
        cudaFuncSetAttribute(gemm_v4_tn<true>,  cudaFuncAttributeMaxDynamicSharedMemorySize, GV_SMEM);
        init = true;
    }

    // 1) LayerNorm
    ln_kernel<<<MTOT, 256>>>(x, gamma, beta);

    // 2) QKV projection: [8192,1024] x [3072,1024]^T -> [8192,3072]
    gemm_v4_tn<false><<<dim3(QKVN / 128, MTOT / 128), 256, GV_SMEM>>>(xn, w_qkv, nullptr, qkv, QKVN, DMODEL);

    // 3) Attention (tf32 MMA flash, 128-q tiles, K/V reg-prefetch)
    attn_kernel<<<dim3(SEQ / 128, BATCH * NHEAD), 256, ATTN_SMEM>>>();

    // 4) Output projection + bias: [8192,1024] x [1024,1024]^T -> [8192,1024]
    gemm_v4_tn<true><<<dim3(DMODEL / 128, MTOT / 128), 256, GV_SMEM>>>(ctx, w_out, b_out, out, DMODEL, DMODEL);
}

// round 16
// speedup vs baseline: 4.4278x; 1.6112x over previous
#include <cuda_runtime.h>
#include <cuda_fp16.h>
#include <math.h>
#include <stdint.h>

#define BATCH  4
#define SEQ    2048
#define DMODEL 1024
#define NHEAD  16
#define HDIM   64
#define MTOT   (BATCH * SEQ)     // 8192
#define QKVN   (3 * DMODEL)      // 3072

// Scratch (device-global statics: allocation-free per harness rules)
static __device__ float g_xn [MTOT * DMODEL];   // 32 MB
static __device__ float g_qkv[MTOT * QKVN];     // 96 MB
static __device__ float g_ctx[MTOT * DMODEL];   // 32 MB

// ---------------------------------------------------------------------------
// FP16 helpers
// ---------------------------------------------------------------------------
__device__ __forceinline__ unsigned f2h2(float lo, float hi)
{
    __half2 h = __floats2half2_rn(lo, hi);   // .x = lo (low 16 bits)
    return *reinterpret_cast<unsigned*>(&h);
}

__device__ __forceinline__ void mma_f16(float* c, const uint4& a, const uint2& b)
{
    asm volatile("mma.sync.aligned.m16n8k16.row.col.f32.f16.f16.f32 "
                 "{%0,%1,%2,%3}, {%4,%5,%6,%7}, {%8,%9}, {%0,%1,%2,%3};\n"
                 : "+f"(c[0]), "+f"(c[1]), "+f"(c[2]), "+f"(c[3])
                 : "r"(a.x), "r"(a.y), "r"(a.z), "r"(a.w),
                   "r"(b.x), "r"(b.y));
}

// ---------------------------------------------------------------------------
// LayerNorm: one block per row (D=1024), 256 threads, float4 per thread
// ---------------------------------------------------------------------------
__global__ __launch_bounds__(256) void ln_kernel(const float* __restrict__ x,
                                                 const float* __restrict__ gamma,
                                                 const float* __restrict__ beta)
{
    const int row = blockIdx.x;
    const int tid = threadIdx.x;
    const float4 v = ((const float4*)(x + (size_t)row * DMODEL))[tid];

    float s  = v.x + v.y + v.z + v.w;
    float s2 = v.x * v.x + v.y * v.y + v.z * v.z + v.w * v.w;
#pragma unroll
    for (int o = 16; o > 0; o >>= 1) {
        s  += __shfl_xor_sync(0xffffffffu, s,  o);
        s2 += __shfl_xor_sync(0xffffffffu, s2, o);
    }
    __shared__ float rs[8], rs2[8], mv[2];
    if ((tid & 31) == 0) { rs[tid >> 5] = s; rs2[tid >> 5] = s2; }
    __syncthreads();
    if (tid == 0) {
        float a = 0.f, b2 = 0.f;
#pragma unroll
        for (int i = 0; i < 8; i++) { a += rs[i]; b2 += rs2[i]; }
        const float mean = a * (1.0f / DMODEL);
        const float var  = b2 * (1.0f / DMODEL) - mean * mean;
        mv[0] = mean;
        mv[1] = rsqrtf(var + 1e-5f);
    }
    __syncthreads();
    const float mean = mv[0], r = mv[1];
    const float4 g  = ((const float4*)gamma)[tid];
    const float4 be = ((const float4*)beta)[tid];
    float4 o;
    o.x = (v.x - mean) * r * g.x + be.x;
    o.y = (v.y - mean) * r * g.y + be.y;
    o.z = (v.z - mean) * r * g.z + be.z;
    o.w = (v.w - mean) * r * g.w + be.w;
    ((float4*)(g_xn + (size_t)row * DMODEL))[tid] = o;
}

// ===========================================================================
// FP16 MMA GEMM v5: C[m,n] = sum_k A[m,k]*B[n,k] (+bias[n])
// CTA 128x128x32, 256 threads = 8 warps (wm 2 x wn 4), warp tile 64x32.
// m16n8k16: k-chunk 32 = 2 ks-steps. j-outer planes, f16x2 words.
// All fragment-smem stores are 32-bit (stride 33 is odd -> no 8B alignment).
// ===========================================================================
#define GH_APLANE  532
#define GH_BPLANE  1060
#define GH_AREG    (4 * GH_APLANE)            // 2128
#define GH_STAGE   (GH_AREG + 2 * GH_BPLANE)  // 4248
#define GH_SMEM    (2 * GH_STAGE * 4)         // 33984 B

template <bool HAS_BIAS>
__global__ __launch_bounds__(256, 2) void gemm_f16_tn(const float* __restrict__ A,
                                                      const float* __restrict__ Bm,
                                                      const float* __restrict__ bias,
                                                      float* __restrict__ C,
                                                      int N, int K)
{
    extern __shared__ unsigned sw[];

    const int tid  = threadIdx.x;
    const int lane = tid & 31;
    const int wid  = tid >> 5;
    const int wm   = wid >> 2;          // 0..1
    const int wn   = wid & 3;           // 0..3
    const int bm   = blockIdx.y * 128;
    const int bn   = blockIdx.x * 128;

    // loader: thread owns half-row (row = tid>>1, k-half = tid&1)
    const int arow = tid >> 1;
    const int ak0  = (tid & 1) * 16;
    const float* Ap = A  + (size_t)(bm + arow) * K + ak0;
    const float* Bp = Bm + (size_t)(bn + arow) * K + ak0;

    int aoffw[4], boffw[4];
    {
        const int mbA = arow >> 4, agr = arow & 7, rowhi = (arow >> 3) & 1;
        const int nbB = arow >> 3, bgr = arow & 7;
#pragma unroll
        for (int q = 0; q < 4; q++) {
            const int k0 = ak0 + 4 * q;
            const int ks = k0 >> 4;
            const int p0 = (k0 >> 1) & 7;
            const int gc0 = p0 & 3, jk = p0 >> 2;
            aoffw[q] = (2 * jk + rowhi) * GH_APLANE + ((mbA * 2 + ks) * 33 + agr * 4 + gc0);
            boffw[q] = GH_AREG + jk * GH_BPLANE + ((nbB * 2 + ks) * 33 + bgr * 4 + gc0);
        }
    }

    float acc[4][4][4] = {};
    const int nc = K >> 5;

    // prologue: chunk 0 -> stage 0
    {
        float4 av[4], bv[4];
#pragma unroll
        for (int q = 0; q < 4; q++) { av[q] = *(const float4*)(Ap + q * 4);
                                      bv[q] = *(const float4*)(Bp + q * 4); }
#pragma unroll
        for (int q = 0; q < 4; q++) {
            sw[aoffw[q]    ] = f2h2(av[q].x, av[q].y);
            sw[aoffw[q] + 1] = f2h2(av[q].z, av[q].w);
            sw[boffw[q]    ] = f2h2(bv[q].x, bv[q].y);
            sw[boffw[q] + 1] = f2h2(bv[q].z, bv[q].w);
        }
    }
    __syncthreads();

    for (int c = 0; c < nc; c++) {
        const bool more = (c + 1 < nc);
        float4 av[4], bv[4];
        if (more) {
            const int kc = (c + 1) * 32;
#pragma unroll
            for (int q = 0; q < 4; q++) { av[q] = *(const float4*)(Ap + kc + q * 4);
                                          bv[q] = *(const float4*)(Bp + kc + q * 4); }
        }

        const unsigned* bufc = sw + (c & 1) * GH_STAGE;
#pragma unroll
        for (int ks = 0; ks < 2; ks++) {
            uint4 a[4];
            uint2 b[4];
#pragma unroll
            for (int mi = 0; mi < 4; mi++) {
                const int base = ((wm * 4 + mi) * 2 + ks) * 33 + lane;
                a[mi] = make_uint4(bufc[base],
                                   bufc[GH_APLANE     + base],
                                   bufc[2 * GH_APLANE + base],
                                   bufc[3 * GH_APLANE + base]);
            }
#pragma unroll
            for (int ni = 0; ni < 4; ni++) {
                const int base = GH_AREG + ((wn * 4 + ni) * 2 + ks) * 33 + lane;
                b[ni] = make_uint2(bufc[base], bufc[GH_BPLANE + base]);
            }
#pragma unroll
            for (int mi = 0; mi < 4; mi++)
#pragma unroll
                for (int ni = 0; ni < 4; ni++)
                    mma_f16(acc[mi][ni], a[mi], b[ni]);
        }

        if (more) {
            unsigned* bufn = sw + ((c + 1) & 1) * GH_STAGE;
#pragma unroll
            for (int q = 0; q < 4; q++) {
                bufn[aoffw[q]    ] = f2h2(av[q].x, av[q].y);
                bufn[aoffw[q] + 1] = f2h2(av[q].z, av[q].w);
                bufn[boffw[q]    ] = f2h2(bv[q].x, bv[q].y);
                bufn[boffw[q] + 1] = f2h2(bv[q].z, bv[q].w);
            }
        }
        __syncthreads();
    }

    // epilogue (C layout same as m16n8k8)
    const int gr = lane >> 2, gc = lane & 3;
#pragma unroll
    for (int mi = 0; mi < 4; mi++) {
        const int row0 = bm + wm * 64 + mi * 16 + gr;
#pragma unroll
        for (int ni = 0; ni < 4; ni++) {
            const int col = bn + wn * 32 + ni * 8 + 2 * gc;
            float b0 = 0.f, b1 = 0.f;
            if (HAS_BIAS) { b0 = bias[col]; b1 = bias[col + 1]; }
            float2 v0, v1;
            v0.x = acc[mi][ni][0] + b0; v0.y = acc[mi][ni][1] + b1;
            v1.x = acc[mi][ni][2] + b0; v1.y = acc[mi][ni][3] + b1;
            *(float2*)&C[(size_t)row0 * N + col]       = v0;
            *(float2*)&C[(size_t)(row0 + 8) * N + col] = v1;
        }
    }
}

// ---------------------------------------------------------------------------
// FP16 MMA flash attention v4: CTA = 128 q-rows of one (b,h); 256 threads
// (8 warps). kv chunks of 64, K/V register-prefetch. m16n8k16.
// All fragment-smem stores 32-bit.
// ---------------------------------------------------------------------------
#define AQ_PLANE  1060
#define AK_PLANE  1060
#define AV_PLANE  1060
#define AP_PLANE  1028
#define A_QBASE   0
#define A_KBASE   (4 * AQ_PLANE)                 // 4240
#define A_VBASE   (A_KBASE + 2 * AK_PLANE)       // 6360
#define A_PBASE   (A_VBASE + 2 * AV_PLANE)       // 8480
#define ATTN_SMEM ((A_PBASE + 4 * AP_PLANE) * 4) // 50368 B

__global__ __launch_bounds__(256, 2) void attn_kernel()
{
    extern __shared__ unsigned fr[];

    const int qt   = blockIdx.x;
    const int bh   = blockIdx.y;
    const int b    = bh >> 4;
    const int h    = bh & 15;
    const int tid  = threadIdx.x;
    const int lane = tid & 31;
    const int wid  = tid >> 5;      // 0..7
    const int gr   = lane >> 2;
    const int gc   = lane & 3;

    const int qoff  = h * HDIM;
    const int koff  = DMODEL + h * HDIM;
    const int voff  = 2 * DMODEL + h * HDIM;
    const int qbase = b * SEQ + qt * 128;
    const int kvbas = b * SEQ;

    // ---- load Q once (scale 1/8 folded): thread owns half-row
    {
        const int lrow = tid >> 1;            // 0..127
        const int ld0  = (tid & 1) * 32;
        const int mb = lrow >> 4, qgr = lrow & 7, rowhi = (lrow >> 3) & 1;
        const float* src = g_qkv + (size_t)(qbase + lrow) * QKVN + qoff + ld0;
#pragma unroll
        for (int q = 0; q < 8; q++) {
            const int d0 = ld0 + q * 4;
            const int ks = d0 >> 4;
            const int p0 = (d0 >> 1) & 7;
            const int gc0 = p0 & 3, jk = p0 >> 2;
            const float4 v = *(const float4*)(src + q * 4);
            const int addr = (2 * jk + rowhi) * AQ_PLANE + ((mb * 4 + ks) * 33 + qgr * 4 + gc0);
            fr[addr    ] = f2h2(v.x * 0.125f, v.y * 0.125f);
            fr[addr + 1] = f2h2(v.z * 0.125f, v.w * 0.125f);
        }
    }

    float m_run[2] = {-INFINITY, -INFINITY};
    float l_run[2] = {0.f, 0.f};
    float oacc[8][4] = {};

    // ---- K loader geometry: thread owns quarter-row (16 d-floats)
    const int kvrow = tid >> 2;           // 0..63
    const int kld0  = (tid & 3) * 16;
    int koffw[4];
    {
        const int knb = kvrow >> 3, kgr = kvrow & 7;
#pragma unroll
        for (int q = 0; q < 4; q++) {
            const int d0 = kld0 + q * 4;
            const int ks = d0 >> 4;
            const int p0 = (d0 >> 1) & 7;
            koffw[q] = A_KBASE + (p0 >> 2) * AK_PLANE + ((knb * 4 + ks) * 33 + kgr * 4 + (p0 & 3));
        }
    }
    // ---- V loader geometry: thread owns kv-pair x 8 d values
    const int vpr   = tid >> 3;           // 0..31 (kv pair)
    const int vkv0  = vpr * 2;
    const int vnd   = tid & 7;            // d block
    const int vdseg = vnd * 8;
    int voffw;                            // base word for s=0
    {
        const int pp = vpr & 7, ksv = vpr >> 3;
        voffw = A_VBASE + (pp >> 2) * AV_PLANE + ((vnd * 4 + ksv) * 33 + (pp & 3));
    }

    float4 kreg[4], v0a, v0b, v1a, v1b;
    // prologue: fetch chunk 0 K/V
    {
        const float* srck = g_qkv + (size_t)(kvbas + kvrow) * QKVN + koff + kld0;
#pragma unroll
        for (int q = 0; q < 4; q++) kreg[q] = *(const float4*)(srck + q * 4);
        const float* srcv0 = g_qkv + (size_t)(kvbas + vkv0) * QKVN + voff + vdseg;
        const float* srcv1 = g_qkv + (size_t)(kvbas + vkv0 + 1) * QKVN + voff + vdseg;
        v0a = *(const float4*)(srcv0);  v0b = *(const float4*)(srcv0 + 4);
        v1a = *(const float4*)(srcv1);  v1b = *(const float4*)(srcv1 + 4);
    }

    for (int kt = 0; kt < SEQ / 64; kt++) {
        __syncthreads();   // previous chunk's MMAs done before overwriting K/V

        // ---- scatter prefetched K/V into fragment smem (32-bit stores)
#pragma unroll
        for (int q = 0; q < 4; q++) {
            fr[koffw[q]    ] = f2h2(kreg[q].x, kreg[q].y);
            fr[koffw[q] + 1] = f2h2(kreg[q].z, kreg[q].w);
        }
        fr[voffw     ] = f2h2(v0a.x, v1a.x);
        fr[voffw +  4] = f2h2(v0a.y, v1a.y);
        fr[voffw +  8] = f2h2(v0a.z, v1a.z);
        fr[voffw + 12] = f2h2(v0a.w, v1a.w);
        fr[voffw + 16] = f2h2(v0b.x, v1b.x);
        fr[voffw + 20] = f2h2(v0b.y, v1b.y);
        fr[voffw + 24] = f2h2(v0b.z, v1b.z);
        fr[voffw + 28] = f2h2(v0b.w, v1b.w);
        __syncthreads();

        // ---- issue next chunk's LDGs (drain under MMA + softmax)
        if (kt + 1 < SEQ / 64) {
            const float* srck = g_qkv + (size_t)(kvbas + (kt + 1) * 64 + kvrow) * QKVN + koff + kld0;
#pragma unroll
            for (int q = 0; q < 4; q++) kreg[q] = *(const float4*)(srck + q * 4);
            const float* srcv0 = g_qkv + (size_t)(kvbas + (kt + 1) * 64 + vkv0) * QKVN + voff + vdseg;
            const float* srcv1 = g_qkv + (size_t)(kvbas + (kt + 1) * 64 + vkv0 + 1) * QKVN + voff + vdseg;
            v0a = *(const float4*)(srcv0);  v0b = *(const float4*)(srcv0 + 4);
            v1a = *(const float4*)(srcv1);  v1b = *(const float4*)(srcv1 + 4);
        }

        // ---- S = Q K^T (warp: 16 x 64 over d=64, 4 ks-steps)
        float sacc[8][4] = {};
#pragma unroll
        for (int ks = 0; ks < 4; ks++) {
            const int abase = (wid * 4 + ks) * 33 + lane;
            const uint4 av = make_uint4(fr[abase],
                                        fr[AQ_PLANE     + abase],
                                        fr[2 * AQ_PLANE + abase],
                                        fr[3 * AQ_PLANE + abase]);
#pragma unroll
            for (int nf = 0; nf < 8; nf++) {
                const int bbase = A_KBASE + (nf * 4 + ks) * 33 + lane;
                const uint2 bv = make_uint2(fr[bbase], fr[AK_PLANE + bbase]);
                mma_f16(sacc[nf], av, bv);
            }
        }

        // ---- online softmax on C-frags (rows gr, gr+8)
        float mlo = -INFINITY, mhi = -INFINITY;
#pragma unroll
        for (int nf = 0; nf < 8; nf++) {
            mlo = fmaxf(mlo, fmaxf(sacc[nf][0], sacc[nf][1]));
            mhi = fmaxf(mhi, fmaxf(sacc[nf][2], sacc[nf][3]));
        }
#pragma unroll
        for (int o = 1; o <= 2; o <<= 1) {
            mlo = fmaxf(mlo, __shfl_xor_sync(0xffffffffu, mlo, o));
            mhi = fmaxf(mhi, __shfl_xor_sync(0xffffffffu, mhi, o));
        }
        const float mnlo = fmaxf(m_run[0], mlo);
        const float mnhi = fmaxf(m_run[1], mhi);
        const float flo  = __expf(m_run[0] - mnlo);
        const float fhi  = __expf(m_run[1] - mnhi);
        m_run[0] = mnlo; m_run[1] = mnhi;

        float rslo = 0.f, rshi = 0.f;
#pragma unroll
        for (int nf = 0; nf < 8; nf++) {
            float p0 = __expf(sacc[nf][0] - mnlo);
            float p1 = __expf(sacc[nf][1] - mnlo);
            float p2 = __expf(sacc[nf][2] - mnhi);
            float p3 = __expf(sacc[nf][3] - mnhi);
            rslo += p0 + p1;
            rshi += p2 + p3;
            // P scatter: A-frag for PV. u = kv-pair index = nf*4+gc
            const int u = nf * 4 + gc;
            const int pp = u & 7, ksv = u >> 3;
            const int jk = pp >> 2;
            const int ip = A_PBASE + (2 * jk) * AP_PLANE + ((wid * 4 + ksv) * 32 + gr * 4 + (pp & 3));
            fr[ip]            = f2h2(p0, p1);   // row gr
            fr[ip + AP_PLANE] = f2h2(p2, p3);   // row gr+8
        }
#pragma unroll
        for (int o = 1; o <= 2; o <<= 1) {
            rslo += __shfl_xor_sync(0xffffffffu, rslo, o);
            rshi += __shfl_xor_sync(0xffffffffu, rshi, o);
        }
        l_run[0] = l_run[0] * flo + rslo;
        l_run[1] = l_run[1] * fhi + rshi;
#pragma unroll
        for (int nd = 0; nd < 8; nd++) {
            oacc[nd][0] *= flo; oacc[nd][1] *= flo;
            oacc[nd][2] *= fhi; oacc[nd][3] *= fhi;
        }
        __syncwarp();   // Pf region is warp-private

        // ---- O += P V (warp: 16 x 64 over kv=64, 4 ksv-steps)
#pragma unroll
        for (int ksv = 0; ksv < 4; ksv++) {
            const int abase = A_PBASE + (wid * 4 + ksv) * 32 + lane;
            const uint4 av = make_uint4(fr[abase],
                                        fr[AP_PLANE     + abase],
                                        fr[2 * AP_PLANE + abase],
                                        fr[3 * AP_PLANE + abase]);
#pragma unroll
            for (int nd = 0; nd < 8; nd++) {
                const int bbase = A_VBASE + (nd * 4 + ksv) * 33 + lane;
                const uint2 bv = make_uint2(fr[bbase], fr[AV_PLANE + bbase]);
                mma_f16(oacc[nd], av, bv);
            }
        }
    }

    // ---- normalize + write ctx
    const float invlo = 1.0f / l_run[0];
    const float invhi = 1.0f / l_run[1];
    const int row_lo = qbase + wid * 16 + gr;
#pragma unroll
    for (int nd = 0; nd < 8; nd++) {
        const int col = h * HDIM + nd * 8 + 2 * gc;
        float2 v0, v1;
        v0.x = oacc[nd][0] * invlo; v0.y = oacc[nd][1] * invlo;
        v1.x = oacc[nd][2] * invhi; v1.y = oacc[nd][3] * invhi;
        *(float2*)&g_ctx[(size_t)row_lo * DMODEL + col]       = v0;
        *(float2*)&g_ctx[(size_t)(row_lo + 8) * DMODEL + col] = v1;
    }
}

// ---------------------------------------------------------------------------
extern "C" void kernel_launch(void* const* d_in, const int* in_sizes, int n_in,
                              void* d_out, int out_size)
{
    const float* x      = (const float*)d_in[0];
    const float* gamma  = (const float*)d_in[1];
    const float* beta   = (const float*)d_in[2];
    const float* w_qkv  = (const float*)d_in[3];
    const float* w_out  = (const float*)d_in[4];
    const float* b_out  = (const float*)d_in[5];
    float* out = (float*)d_out;

    static float* xn  = nullptr;
    static float* qkv = nullptr;
    static float* ctx = nullptr;
    static bool init = false;
    if (!init) {
        cudaGetSymbolAddress((void**)&xn,  g_xn);
        cudaGetSymbolAddress((void**)&qkv, g_qkv);
        cudaGetSymbolAddress((void**)&ctx, g_ctx);
        cudaFuncSetAttribute(attn_kernel, cudaFuncAttributeMaxDynamicSharedMemorySize, ATTN_SMEM);
        cudaFuncSetAttribute(gemm_f16_tn<false>, cudaFuncAttributeMaxDynamicSharedMemorySize, GH_SMEM);
        cudaFuncSetAttribute(gemm_f16_tn<true>,  cudaFuncAttributeMaxDynamicSharedMemorySize, GH_SMEM);
        init = true;
    }

    // 1) LayerNorm
    ln_kernel<<<MTOT, 256>>>(x, gamma, beta);

    // 2) QKV projection: [8192,1024] x [3072,1024]^T -> [8192,3072]  (fp16 MMA)
    gemm_f16_tn<false><<<dim3(QKVN / 128, MTOT / 128), 256, GH_SMEM>>>(xn, w_qkv, nullptr, qkv, QKVN, DMODEL);

    // 3) Attention (fp16 MMA flash, 128-q tiles, K/V reg-prefetch)
    attn_kernel<<<dim3(SEQ / 128, BATCH * NHEAD), 256, ATTN_SMEM>>>();

    // 4) Output projection + bias: [8192,1024] x [1024,1024]^T -> [8192,1024]  (fp16 MMA)
    gemm_f16_tn<true><<<dim3(DMODEL / 128, MTOT / 128), 256, GH_SMEM>>>(ctx, w_out, b_out, out, DMODEL, DMODEL);
}

// round 17
// speedup vs baseline: 5.1634x; 1.1661x over previous
#include <cuda_runtime.h>
#include <cuda_fp16.h>
#include <math.h>
#include <stdint.h>

#define BATCH  4
#define SEQ    2048
#define DMODEL 1024
#define NHEAD  16
#define HDIM   64
#define MTOT   (BATCH * SEQ)     // 8192
#define QKVN   (3 * DMODEL)      // 3072

// Scratch (device-global statics: allocation-free per harness rules)
static __device__ __half g_xn_h [MTOT * DMODEL];   // 16 MB
static __device__ __half g_qkv_h[MTOT * QKVN];     // 48 MB
static __device__ __half g_ctx_h[MTOT * DMODEL];   // 16 MB
static __device__ __half g_wqkv_h[QKVN * DMODEL];  // 6 MB
static __device__ __half g_wout_h[DMODEL * DMODEL];// 2 MB

// ---------------------------------------------------------------------------
// helpers
// ---------------------------------------------------------------------------
__device__ __forceinline__ unsigned f2h2(float lo, float hi)
{
    __half2 h = __floats2half2_rn(lo, hi);
    return *reinterpret_cast<unsigned*>(&h);
}

__device__ __forceinline__ unsigned hscale8(unsigned w)   // * 0.125 (exact)
{
    __half2 h = *reinterpret_cast<__half2*>(&w);
    h = __hmul2(h, __floats2half2_rn(0.125f, 0.125f));
    return *reinterpret_cast<unsigned*>(&h);
}

__device__ __forceinline__ void mma_f16(float* c, const uint4& a, const uint2& b)
{
    asm volatile("mma.sync.aligned.m16n8k16.row.col.f32.f16.f16.f32 "
                 "{%0,%1,%2,%3}, {%4,%5,%6,%7}, {%8,%9}, {%0,%1,%2,%3};\n"
                 : "+f"(c[0]), "+f"(c[1]), "+f"(c[2]), "+f"(c[3])
                 : "r"(a.x), "r"(a.y), "r"(a.z), "r"(a.w),
                   "r"(b.x), "r"(b.y));
}

__device__ __forceinline__ void cp8(uint32_t dst, const void* src)
{
    asm volatile("cp.async.ca.shared.global [%0], [%1], 8;\n" :: "r"(dst), "l"(src));
}
#define CP_COMMIT() asm volatile("cp.async.commit_group;\n" ::: "memory")
#define CP_WAIT(n)  asm volatile("cp.async.wait_group %0;\n" :: "n"(n) : "memory")

// ---------------------------------------------------------------------------
// fp32 -> fp16 conversion (weights)
// ---------------------------------------------------------------------------
__global__ __launch_bounds__(256) void cvt_kernel(const float* __restrict__ src,
                                                  __half* __restrict__ dst, int n4)
{
    const int i = blockIdx.x * 256 + threadIdx.x;
    if (i < n4) {
        const float4 v = ((const float4*)src)[i];
        ((uint2*)dst)[i] = make_uint2(f2h2(v.x, v.y), f2h2(v.z, v.w));
    }
}

// ---------------------------------------------------------------------------
// LayerNorm -> fp16 output
// ---------------------------------------------------------------------------
__global__ __launch_bounds__(256) void ln_kernel(const float* __restrict__ x,
                                                 const float* __restrict__ gamma,
                                                 const float* __restrict__ beta)
{
    const int row = blockIdx.x;
    const int tid = threadIdx.x;
    const float4 v = ((const float4*)(x + (size_t)row * DMODEL))[tid];

    float s  = v.x + v.y + v.z + v.w;
    float s2 = v.x * v.x + v.y * v.y + v.z * v.z + v.w * v.w;
#pragma unroll
    for (int o = 16; o > 0; o >>= 1) {
        s  += __shfl_xor_sync(0xffffffffu, s,  o);
        s2 += __shfl_xor_sync(0xffffffffu, s2, o);
    }
    __shared__ float rs[8], rs2[8], mv[2];
    if ((tid & 31) == 0) { rs[tid >> 5] = s; rs2[tid >> 5] = s2; }
    __syncthreads();
    if (tid == 0) {
        float a = 0.f, b2 = 0.f;
#pragma unroll
        for (int i = 0; i < 8; i++) { a += rs[i]; b2 += rs2[i]; }
        const float mean = a * (1.0f / DMODEL);
        const float var  = b2 * (1.0f / DMODEL) - mean * mean;
        mv[0] = mean;
        mv[1] = rsqrtf(var + 1e-5f);
    }
    __syncthreads();
    const float mean = mv[0], r = mv[1];
    const float4 g  = ((const float4*)gamma)[tid];
    const float4 be = ((const float4*)beta)[tid];
    float ox = (v.x - mean) * r * g.x + be.x;
    float oy = (v.y - mean) * r * g.y + be.y;
    float oz = (v.z - mean) * r * g.z + be.z;
    float ow = (v.w - mean) * r * g.w + be.w;
    ((uint2*)(g_xn_h + (size_t)row * DMODEL))[tid] = make_uint2(f2h2(ox, oy), f2h2(oz, ow));
}

// ===========================================================================
// FP16 GEMM v6 (cp.async): C[m,n] = sum_k A[m,k]*B[n,k] (+bias)
// A,B fp16 row-major. CTA 128x128x32, 256 thr = 8 warps (2x4), warp 64x32.
// Fragment planes, stride 34 (8B-aligned dst for cp.async), 4-stage ring.
// OUT_HALF: write C as fp16 (no bias), else fp32 + bias.
// ===========================================================================
#define GF_APLANE  546                      // 16 frags * 34 + 2
#define GF_BPLANE  1090                     // 32 frags * 34 + 2
#define GF_AREG    (4 * GF_APLANE)          // 2184
#define GF_STAGE   (GF_AREG + 2 * GF_BPLANE)// 4364 words
#define GF_NSTAGE  4
#define GF_SMEM    (GF_NSTAGE * GF_STAGE * 4)  // 69824 B

template <bool HAS_BIAS, bool OUT_HALF>
__global__ __launch_bounds__(256, 2) void gemm_cp_tn(const __half* __restrict__ A,
                                                     const __half* __restrict__ Bm,
                                                     const float* __restrict__ bias,
                                                     void* __restrict__ C,
                                                     int N, int K)
{
    extern __shared__ unsigned sw[];
    uint32_t swb;
    asm("{ .reg .u64 t; cvta.to.shared.u64 t, %1; cvt.u32.u64 %0, t; }" : "=r"(swb) : "l"(sw));

    const int tid  = threadIdx.x;
    const int lane = tid & 31;
    const int wid  = tid >> 5;
    const int wm   = wid >> 2;          // 0..1
    const int wn   = wid & 3;           // 0..3
    const int bm   = blockIdx.y * 128;
    const int bn   = blockIdx.x * 128;

    // loader geometry: thread owns half-row (row = tid>>1, k-half = tid&1)
    const int arow = tid >> 1;
    const int ak0  = (tid & 1) * 16;
    const char* Abyte = (const char*)(A  + (size_t)(bm + arow) * K + ak0);
    const char* Bbyte = (const char*)(Bm + (size_t)(bn + arow) * K + ak0);

    int aoffw[4], boffw[4];
    {
        const int mbA = arow >> 4, agr = arow & 7, rowhi = (arow >> 3) & 1;
        const int nbB = arow >> 3, bgr = arow & 7;
#pragma unroll
        for (int q = 0; q < 4; q++) {
            const int k0 = ak0 + 4 * q;
            const int ks = k0 >> 4;
            const int p0 = (k0 >> 1) & 7;
            const int gc0 = p0 & 3, jk = p0 >> 2;
            aoffw[q] = (2 * jk + rowhi) * GF_APLANE + ((mbA * 2 + ks) * 34 + agr * 4 + gc0);
            boffw[q] = GF_AREG + jk * GF_BPLANE + ((nbB * 2 + ks) * 34 + bgr * 4 + gc0);
        }
    }

    const int nc = K >> 5;   // 32 chunks

    // ---- prologue: issue stages 0..2
#pragma unroll
    for (int s = 0; s < 3; s++) {
        const uint32_t sb = swb + 4u * (s * GF_STAGE);
#pragma unroll
        for (int q = 0; q < 4; q++) {
            cp8(sb + 4u * aoffw[q], Abyte + s * 64 + q * 8);
            cp8(sb + 4u * boffw[q], Bbyte + s * 64 + q * 8);
        }
        CP_COMMIT();
    }

    float acc[4][4][4] = {};

    for (int c = 0; c < nc; c++) {
        if (c + 1 >= nc)      CP_WAIT(0);
        else if (c + 2 >= nc) CP_WAIT(1);
        else                  CP_WAIT(2);
        __syncthreads();

        const unsigned* bufc = sw + (c & 3) * GF_STAGE;
#pragma unroll
        for (int ks = 0; ks < 2; ks++) {
            uint4 a[4];
            uint2 b[4];
#pragma unroll
            for (int mi = 0; mi < 4; mi++) {
                const int base = ((wm * 4 + mi) * 2 + ks) * 34 + lane;
                a[mi] = make_uint4(bufc[base],
                                   bufc[GF_APLANE     + base],
                                   bufc[2 * GF_APLANE + base],
                                   bufc[3 * GF_APLANE + base]);
            }
#pragma unroll
            for (int ni = 0; ni < 4; ni++) {
                const int base = GF_AREG + ((wn * 4 + ni) * 2 + ks) * 34 + lane;
                b[ni] = make_uint2(bufc[base], bufc[GF_BPLANE + base]);
            }
#pragma unroll
            for (int mi = 0; mi < 4; mi++)
#pragma unroll
                for (int ni = 0; ni < 4; ni++)
                    mma_f16(acc[mi][ni], a[mi], b[ni]);
        }

        if (c + 3 < nc) {
            const int s = c + 3;
            const uint32_t sb = swb + 4u * ((s & 3) * GF_STAGE);
#pragma unroll
            for (int q = 0; q < 4; q++) {
                cp8(sb + 4u * aoffw[q], Abyte + s * 64 + q * 8);
                cp8(sb + 4u * boffw[q], Bbyte + s * 64 + q * 8);
            }
            CP_COMMIT();
        }
    }

    // ---- epilogue
    const int gr = lane >> 2, gc = lane & 3;
#pragma unroll
    for (int mi = 0; mi < 4; mi++) {
        const int row0 = bm + wm * 64 + mi * 16 + gr;
#pragma unroll
        for (int ni = 0; ni < 4; ni++) {
            const int col = bn + wn * 32 + ni * 8 + 2 * gc;
            if (OUT_HALF) {
                unsigned* Ch = (unsigned*)C;
                Ch[((size_t)row0 * N + col) >> 1]       = f2h2(acc[mi][ni][0], acc[mi][ni][1]);
                Ch[((size_t)(row0 + 8) * N + col) >> 1] = f2h2(acc[mi][ni][2], acc[mi][ni][3]);
            } else {
                float* Cf = (float*)C;
                float b0 = 0.f, b1 = 0.f;
                if (HAS_BIAS) { b0 = bias[col]; b1 = bias[col + 1]; }
                float2 v0, v1;
                v0.x = acc[mi][ni][0] + b0; v0.y = acc[mi][ni][1] + b1;
                v1.x = acc[mi][ni][2] + b0; v1.y = acc[mi][ni][3] + b1;
                *(float2*)&Cf[(size_t)row0 * N + col]       = v0;
                *(float2*)&Cf[(size_t)(row0 + 8) * N + col] = v1;
            }
        }
    }
}

// ---------------------------------------------------------------------------
// FP16 MMA flash attention v5: fp16 qkv input, fp16 ctx output.
// Structure/layout identical to validated R16 kernel; loaders read fp16.
// ---------------------------------------------------------------------------
#define AQ_PLANE  1060
#define AK_PLANE  1060
#define AV_PLANE  1060
#define AP_PLANE  1028
#define A_KBASE   (4 * AQ_PLANE)                 // 4240
#define A_VBASE   (A_KBASE + 2 * AK_PLANE)       // 6360
#define A_PBASE   (A_VBASE + 2 * AV_PLANE)       // 8480
#define ATTN_SMEM ((A_PBASE + 4 * AP_PLANE) * 4) // 50368 B

__global__ __launch_bounds__(256, 2) void attn_kernel()
{
    extern __shared__ unsigned fr[];

    const int qt   = blockIdx.x;
    const int bh   = blockIdx.y;
    const int b    = bh >> 4;
    const int h    = bh & 15;
    const int tid  = threadIdx.x;
    const int lane = tid & 31;
    const int wid  = tid >> 5;      // 0..7
    const int gr   = lane >> 2;
    const int gc   = lane & 3;

    const int qoff  = h * HDIM;
    const int koff  = DMODEL + h * HDIM;
    const int voff  = 2 * DMODEL + h * HDIM;
    const int qbase = b * SEQ + qt * 128;
    const int kvbas = b * SEQ;

    // ---- load Q once (x0.125 exact): thread owns half-row (32 halves)
    {
        const int lrow = tid >> 1;
        const int ld0  = (tid & 1) * 32;
        const int mb = lrow >> 4, qgr = lrow & 7, rowhi = (lrow >> 3) & 1;
        const unsigned* src = (const unsigned*)(g_qkv_h + (size_t)(qbase + lrow) * QKVN + qoff + ld0);
        unsigned qw[16];
        *(uint4*)(qw)      = *(const uint4*)(src);
        *(uint4*)(qw + 4)  = *(const uint4*)(src + 4);
        *(uint4*)(qw + 8)  = *(const uint4*)(src + 8);
        *(uint4*)(qw + 12) = *(const uint4*)(src + 12);
#pragma unroll
        for (int q = 0; q < 8; q++) {
            const int d0 = ld0 + q * 4;
            const int ks = d0 >> 4;
            const int p0 = (d0 >> 1) & 7;
            const int gc0 = p0 & 3, jk = p0 >> 2;
            const int addr = (2 * jk + rowhi) * AQ_PLANE + ((mb * 4 + ks) * 33 + qgr * 4 + gc0);
            fr[addr    ] = hscale8(qw[2 * q]);
            fr[addr + 1] = hscale8(qw[2 * q + 1]);
        }
    }

    float m_run[2] = {-INFINITY, -INFINITY};
    float l_run[2] = {0.f, 0.f};
    float oacc[8][4] = {};

    // ---- K loader: thread owns quarter-row (16 halves = 2 uint4)
    const int kvrow = tid >> 2;
    const int kld0  = (tid & 3) * 16;
    int koffw[4];
    {
        const int knb = kvrow >> 3, kgr = kvrow & 7;
#pragma unroll
        for (int q = 0; q < 4; q++) {
            const int d0 = kld0 + q * 4;
            const int ks = d0 >> 4;
            const int p0 = (d0 >> 1) & 7;
            koffw[q] = A_KBASE + (p0 >> 2) * AK_PLANE + ((knb * 4 + ks) * 33 + kgr * 4 + (p0 & 3));
        }
    }
    // ---- V loader: thread owns kv-pair x 8 d (uint4 per row)
    const int vpr   = tid >> 3;
    const int vkv0  = vpr * 2;
    const int vnd   = tid & 7;
    const int vdseg = vnd * 8;
    int voffw;
    {
        const int pp = vpr & 7, ksv = vpr >> 3;
        voffw = A_VBASE + (pp >> 2) * AV_PLANE + ((vnd * 4 + ksv) * 33 + (pp & 3));
    }

    uint4 k0r, k1r, va, vb;
    {
        const unsigned* srck = (const unsigned*)(g_qkv_h + (size_t)(kvbas + kvrow) * QKVN + koff + kld0);
        k0r = *(const uint4*)(srck);
        k1r = *(const uint4*)(srck + 4);
        va = *(const uint4*)(g_qkv_h + (size_t)(kvbas + vkv0) * QKVN + voff + vdseg);
        vb = *(const uint4*)(g_qkv_h + (size_t)(kvbas + vkv0 + 1) * QKVN + voff + vdseg);
    }

    for (int kt = 0; kt < SEQ / 64; kt++) {
        __syncthreads();   // previous chunk's MMAs done before overwriting K/V

        // ---- scatter prefetched K/V (32-bit stores)
        {
            const unsigned kw[8] = {k0r.x, k0r.y, k0r.z, k0r.w, k1r.x, k1r.y, k1r.z, k1r.w};
#pragma unroll
            for (int q = 0; q < 4; q++) {
                fr[koffw[q]    ] = kw[2 * q];
                fr[koffw[q] + 1] = kw[2 * q + 1];
            }
            const unsigned aw[4] = {va.x, va.y, va.z, va.w};
            const unsigned bw[4] = {vb.x, vb.y, vb.z, vb.w};
#pragma unroll
            for (int i = 0; i < 4; i++) {
                fr[voffw + 8 * i    ] = __byte_perm(aw[i], bw[i], 0x5410);
                fr[voffw + 8 * i + 4] = __byte_perm(aw[i], bw[i], 0x7632);
            }
        }
        __syncthreads();

        // ---- issue next chunk's LDGs (drain under MMA + softmax)
        if (kt + 1 < SEQ / 64) {
            const unsigned* srck = (const unsigned*)(g_qkv_h + (size_t)(kvbas + (kt + 1) * 64 + kvrow) * QKVN + koff + kld0);
            k0r = *(const uint4*)(srck);
            k1r = *(const uint4*)(srck + 4);
            va = *(const uint4*)(g_qkv_h + (size_t)(kvbas + (kt + 1) * 64 + vkv0) * QKVN + voff + vdseg);
            vb = *(const uint4*)(g_qkv_h + (size_t)(kvbas + (kt + 1) * 64 + vkv0 + 1) * QKVN + voff + vdseg);
        }

        // ---- S = Q K^T (warp: 16 x 64 over d=64, 4 ks-steps)
        float sacc[8][4] = {};
#pragma unroll
        for (int ks = 0; ks < 4; ks++) {
            const int abase = (wid * 4 + ks) * 33 + lane;
            const uint4 av = make_uint4(fr[abase],
                                        fr[AQ_PLANE     + abase],
                                        fr[2 * AQ_PLANE + abase],
                                        fr[3 * AQ_PLANE + abase]);
#pragma unroll
            for (int nf = 0; nf < 8; nf++) {
                const int bbase = A_KBASE + (nf * 4 + ks) * 33 + lane;
                const uint2 bv = make_uint2(fr[bbase], fr[AK_PLANE + bbase]);
                mma_f16(sacc[nf], av, bv);
            }
        }

        // ---- online softmax on C-frags (rows gr, gr+8)
        float mlo = -INFINITY, mhi = -INFINITY;
#pragma unroll
        for (int nf = 0; nf < 8; nf++) {
            mlo = fmaxf(mlo, fmaxf(sacc[nf][0], sacc[nf][1]));
            mhi = fmaxf(mhi, fmaxf(sacc[nf][2], sacc[nf][3]));
        }
#pragma unroll
        for (int o = 1; o <= 2; o <<= 1) {
            mlo = fmaxf(mlo, __shfl_xor_sync(0xffffffffu, mlo, o));
            mhi = fmaxf(mhi, __shfl_xor_sync(0xffffffffu, mhi, o));
        }
        const float mnlo = fmaxf(m_run[0], mlo);
        const float mnhi = fmaxf(m_run[1], mhi);
        const float flo  = __expf(m_run[0] - mnlo);
        const float fhi  = __expf(m_run[1] - mnhi);
        m_run[0] = mnlo; m_run[1] = mnhi;

        float rslo = 0.f, rshi = 0.f;
#pragma unroll
        for (int nf = 0; nf < 8; nf++) {
            float p0 = __expf(sacc[nf][0] - mnlo);
            float p1 = __expf(sacc[nf][1] - mnlo);
            float p2 = __expf(sacc[nf][2] - mnhi);
            float p3 = __expf(sacc[nf][3] - mnhi);
            rslo += p0 + p1;
            rshi += p2 + p3;
            const int u = nf * 4 + gc;
            const int pp = u & 7, ksv = u >> 3;
            const int jk = pp >> 2;
            const int ip = A_PBASE + (2 * jk) * AP_PLANE + ((wid * 4 + ksv) * 32 + gr * 4 + (pp & 3));
            fr[ip]            = f2h2(p0, p1);   // row gr
            fr[ip + AP_PLANE] = f2h2(p2, p3);   // row gr+8
        }
#pragma unroll
        for (int o = 1; o <= 2; o <<= 1) {
            rslo += __shfl_xor_sync(0xffffffffu, rslo, o);
            rshi += __shfl_xor_sync(0xffffffffu, rshi, o);
        }
        l_run[0] = l_run[0] * flo + rslo;
        l_run[1] = l_run[1] * fhi + rshi;
#pragma unroll
        for (int nd = 0; nd < 8; nd++) {
            oacc[nd][0] *= flo; oacc[nd][1] *= flo;
            oacc[nd][2] *= fhi; oacc[nd][3] *= fhi;
        }
        __syncwarp();   // Pf region is warp-private

        // ---- O += P V (warp: 16 x 64 over kv=64, 4 ksv-steps)
#pragma unroll
        for (int ksv = 0; ksv < 4; ksv++) {
            const int abase = A_PBASE + (wid * 4 + ksv) * 32 + lane;
            const uint4 av = make_uint4(fr[abase],
                                        fr[AP_PLANE     + abase],
                                        fr[2 * AP_PLANE + abase],
                                        fr[3 * AP_PLANE + abase]);
#pragma unroll
            for (int nd = 0; nd < 8; nd++) {
                const int bbase = A_VBASE + (nd * 4 + ksv) * 33 + lane;
                const uint2 bv = make_uint2(fr[bbase], fr[AV_PLANE + bbase]);
                mma_f16(oacc[nd], av, bv);
            }
        }
    }

    // ---- normalize + write ctx (fp16)
    const float invlo = 1.0f / l_run[0];
    const float invhi = 1.0f / l_run[1];
    const int row_lo = qbase + wid * 16 + gr;
    unsigned* ctxw = (unsigned*)g_ctx_h;
#pragma unroll
    for (int nd = 0; nd < 8; nd++) {
        const int col = h * HDIM + nd * 8 + 2 * gc;
        ctxw[((size_t)row_lo * DMODEL + col) >> 1]       = f2h2(oacc[nd][0] * invlo, oacc[nd][1] * invlo);
        ctxw[((size_t)(row_lo + 8) * DMODEL + col) >> 1] = f2h2(oacc[nd][2] * invhi, oacc[nd][3] * invhi);
    }
}

// ---------------------------------------------------------------------------
extern "C" void kernel_launch(void* const* d_in, const int* in_sizes, int n_in,
                              void* d_out, int out_size)
{
    const float* x      = (const float*)d_in[0];
    const float* gamma  = (const float*)d_in[1];
    const float* beta   = (const float*)d_in[2];
    const float* w_qkv  = (const float*)d_in[3];
    const float* w_out  = (const float*)d_in[4];
    const float* b_out  = (const float*)d_in[5];
    float* out = (float*)d_out;

    static __half *xn = nullptr, *qkv = nullptr, *ctx = nullptr, *wq = nullptr, *wo = nullptr;
    static bool init = false;
    if (!init) {
        cudaGetSymbolAddress((void**)&xn,  g_xn_h);
        cudaGetSymbolAddress((void**)&qkv, g_qkv_h);
        cudaGetSymbolAddress((void**)&ctx, g_ctx_h);
        cudaGetSymbolAddress((void**)&wq,  g_wqkv_h);
        cudaGetSymbolAddress((void**)&wo,  g_wout_h);
        cudaFuncSetAttribute(attn_kernel, cudaFuncAttributeMaxDynamicSharedMemorySize, ATTN_SMEM);
        cudaFuncSetAttribute(gemm_cp_tn<false, true>,  cudaFuncAttributeMaxDynamicSharedMemorySize, GF_SMEM);
        cudaFuncSetAttribute(gemm_cp_tn<true,  false>, cudaFuncAttributeMaxDynamicSharedMemorySize, GF_SMEM);
        init = true;
    }

    // 0) convert weights to fp16
    cvt_kernel<<<(QKVN * DMODEL / 4 + 255) / 256, 256>>>(w_qkv, wq, QKVN * DMODEL / 4);
    cvt_kernel<<<(DMODEL * DMODEL / 4 + 255) / 256, 256>>>(w_out, wo, DMODEL * DMODEL / 4);

    // 1) LayerNorm (fp16 out)
    ln_kernel<<<MTOT, 256>>>(x, gamma, beta);

    // 2) QKV projection -> fp16 qkv
    gemm_cp_tn<false, true><<<dim3(QKVN / 128, MTOT / 128), 256, GF_SMEM>>>(xn, wq, nullptr, qkv, QKVN, DMODEL);

    // 3) Attention (fp16 in/out)
    attn_kernel<<<dim3(SEQ / 128, BATCH * NHEAD), 256, ATTN_SMEM>>>();

    // 4) Output projection + bias -> fp32 out
    gemm_cp_tn<true, false><<<dim3(DMODEL / 128, MTOT / 128), 256, GF_SMEM>>>(ctx, wo, b_out, out, DMODEL, DMODEL);
}